// round 11
// baseline (speedup 1.0000x reference)
#include <cuda_runtime.h>
#include <cuda_fp16.h>
#include <cstdint>

// ---------------------------------------------------------------------------
// VQ-VAE vector quantizer, GB300 sm_103a (sm_103-generic toolchain).
// R10 core + fused epilogue: k_mma now does (reduce -> in-CTA exact fix of
// contested rows -> gather/scatter) for its own 128 rows. k_fix/k_gather
// kernels removed. Mainloop (fold BEFORE sync/issue, unroll 2) untouched.
// ---------------------------------------------------------------------------

#define N_ROWS   32768
#define K_CODES  1024
#define D_DIM    256

#define OFF_LOSS 8388608
#define OFF_IDX  8388609
#define OFF_EMB  8421377
#define OFF_CS   8683521
#define OFF_ES   8684545

#define THETA    2.5e-4f

__device__ float   g_enorm[K_CODES];
__device__ float   g_counts[K_CODES];
__device__ float4  g_embed_sum4[K_CODES * 64];
__device__ __half  g_E16[K_CODES * D_DIM];
__device__ float   g_loss;

// ---------------- helpers --------------------------------------------------
__device__ __forceinline__ uint32_t smem_to_u32(const void* p) {
    uint32_t a;
    asm("{ .reg .u64 t; cvta.to.shared.u64 t, %1; cvt.u32.u64 %0, t; }"
        : "=r"(a) : "l"(p));
    return a;
}

__device__ __forceinline__ void ldm4(uint32_t r[4], uint32_t addr) {
    asm volatile("ldmatrix.sync.aligned.m8n8.x4.shared.b16 {%0,%1,%2,%3}, [%4];"
                 : "=r"(r[0]), "=r"(r[1]), "=r"(r[2]), "=r"(r[3]) : "r"(addr));
}

__device__ __forceinline__ void mma16816(float c[4], const uint32_t a[4],
                                         uint32_t b0, uint32_t b1) {
    asm volatile(
        "mma.sync.aligned.m16n8k16.row.col.f32.f16.f16.f32 "
        "{%0,%1,%2,%3}, {%4,%5,%6,%7}, {%8,%9}, {%0,%1,%2,%3};"
        : "+f"(c[0]), "+f"(c[1]), "+f"(c[2]), "+f"(c[3])
        : "r"(a[0]), "r"(a[1]), "r"(a[2]), "r"(a[3]), "r"(b0), "r"(b1));
}

// ---------------------------------------------------------------------------
// Kernel 1: ||e||^2, E -> fp16, zero scratch
// ---------------------------------------------------------------------------
__global__ void k_init(const float* __restrict__ E, float* __restrict__ out) {
    const int k = blockIdx.x;
    const int t = threadIdx.x;
    float v = E[k * D_DIM + t];
    g_E16[k * D_DIM + t] = __float2half_rn(v);
    float s = v * v;
    #pragma unroll
    for (int o = 16; o; o >>= 1) s += __shfl_down_sync(0xffffffffu, s, o);
    __shared__ float ws[8];
    if ((t & 31) == 0) ws[t >> 5] = s;
    __syncthreads();
    if (t == 0) {
        float tot = 0.f;
        #pragma unroll
        for (int i = 0; i < 8; ++i) tot += ws[i];
        g_enorm[k]  = tot;
        g_counts[k] = 0.f;
        if (k == 0) g_loss = 0.f;
    }
    ((float*)g_embed_sum4)[k * 256 + t] = 0.f;
}

// ---------------------------------------------------------------------------
// Kernel 2: fp16 mma.sync GEMM (128 rows/CTA x 1024 codes, D=256) + fused
// exact fix + gather/scatter epilogue.
// ---------------------------------------------------------------------------
#define SM_A   0
#define SM_B   65536
#define SM_EN  196608
#define SM_RED SM_B
#define SMEM_MMA_TOTAL 200704

__global__ __launch_bounds__(256, 1)
void k_mma(const float* __restrict__ z, const float* __restrict__ E,
           float* __restrict__ out) {
    extern __shared__ char smem[];
    __shared__ int   s_idx[128];
    __shared__ int   s_cnl[128];
    __shared__ int   s_cc;
    __shared__ float ws2[8];
    const uint32_t sb = smem_to_u32(smem);
    const int tid  = threadIdx.x;
    const int warp = tid >> 5;
    const int lane = tid & 31;
    const int n0  = blockIdx.x * 128;
    const int b   = n0 >> 10;
    const int hw0 = n0 & 1023;

    // ---- prologue: A tile (z rows -> fp16, swizzled row-major [row][d]) ----
    const float4* zb4 = (const float4*)(z + (size_t)b * 262144 + hw0);
    #pragma unroll 4
    for (int i = 0; i < 16; ++i) {
        int f  = i * 256 + tid;
        int d2 = f >> 5;
        int r4 = f & 31;
        float4 v0 = zb4[(2 * d2) * 256 + r4];
        float4 v1 = zb4[(2 * d2 + 1) * 256 + r4];
        float a0[4] = {v0.x, v0.y, v0.z, v0.w};
        float a1[4] = {v1.x, v1.y, v1.z, v1.w};
        #pragma unroll
        for (int j = 0; j < 4; ++j) {
            int row = r4 * 4 + j;
            uint32_t off = ((uint32_t)row << 9) | ((uint32_t)d2 << 2);
            off ^= (uint32_t)(row & 7) << 4;
            *(__half2*)(smem + off) = __floats2half2_rn(a0[j], a1[j]);
        }
    }
    float* s_en = (float*)(smem + SM_EN);
    #pragma unroll
    for (int i = 0; i < 4; ++i) s_en[tid + i * 256] = g_enorm[tid + i * 256];

    auto issue = [&](int c) {
        const __half* src = g_E16 + (size_t)c * 128 * 256;
        const uint32_t base = sb + SM_B + (uint32_t)(c & 1) * 65536;
        #pragma unroll
        for (int i = 0; i < 16; ++i) {
            int lin  = tid + i * 256;
            int code = lin >> 5, d8 = lin & 31;
            uint32_t off = ((uint32_t)code << 9) + ((uint32_t)d8 << 4);
            off ^= (uint32_t)(code & 7) << 4;
            const void* g = src + code * 256 + d8 * 8;
            asm volatile("cp.async.cg.shared.global [%0], [%1], 16;"
                         :: "r"(base + off), "l"(g));
        }
        asm volatile("cp.async.commit_group;" ::: "memory");
    };
    issue(0);
    issue(1);
    __syncthreads();

    const int mw = warp & 3;
    const int nc = warp >> 2;
    const int mat = lane >> 3, rwi = lane & 7;

    uint32_t aBase[2], aXor[2];
    #pragma unroll
    for (int mt = 0; mt < 2; ++mt) {
        int row = mw * 32 + mt * 16 + rwi + ((mat & 1) << 3);
        aBase[mt] = sb + ((uint32_t)row << 9);
        aXor[mt]  = (uint32_t)(row & 7) << 4;
    }
    const uint32_t aK = (uint32_t)(mat >> 1) << 4;

    uint32_t bBase[4], bXor[4];
    #pragma unroll
    for (int np = 0; np < 4; ++np) {
        int code = nc * 64 + np * 16 + rwi + ((mat >> 1) << 3);
        bBase[np] = ((uint32_t)code << 9);
        bXor[np]  = (uint32_t)(code & 7) << 4;
    }
    const uint32_t bK = (uint32_t)(mat & 1) << 4;

    float b1[4], b2[4], b3[4];
    int   i1[4], i2[4], i3[4];
    #pragma unroll
    for (int l = 0; l < 4; ++l) {
        b1[l] = b2[l] = b3[l] = 3.4e38f;
        i1[l] = i2[l] = i3[l] = 0;
    }

    for (int c = 0; c < 8; ++c) {
        if (c == 7) asm volatile("cp.async.wait_group 0;" ::: "memory");
        else        asm volatile("cp.async.wait_group 1;" ::: "memory");
        __syncthreads();

        const uint32_t bBuf = sb + SM_B + (uint32_t)(c & 1) * 65536;
        float acc[2][8][4];
        #pragma unroll
        for (int mt = 0; mt < 2; ++mt)
            #pragma unroll
            for (int nt = 0; nt < 8; ++nt)
                #pragma unroll
                for (int q = 0; q < 4; ++q) acc[mt][nt][q] = 0.f;

        #pragma unroll 2
        for (int ks = 0; ks < 16; ++ks) {
            const uint32_t kb = (uint32_t)ks << 5;
            uint32_t af[2][4], bf[4][4];
            #pragma unroll
            for (int mt = 0; mt < 2; ++mt)
                ldm4(af[mt], aBase[mt] + ((kb + aK) ^ aXor[mt]));
            #pragma unroll
            for (int np = 0; np < 4; ++np)
                ldm4(bf[np], bBuf + bBase[np] + ((kb + bK) ^ bXor[np]));
            #pragma unroll
            for (int mt = 0; mt < 2; ++mt)
                #pragma unroll
                for (int np = 0; np < 4; ++np) {
                    mma16816(acc[mt][np * 2],     af[mt], bf[np][0], bf[np][1]);
                    mma16816(acc[mt][np * 2 + 1], af[mt], bf[np][2], bf[np][3]);
                }
        }

        // fold FIRST (consumes acc), then sync, then refill buffer
        #pragma unroll
        for (int mt = 0; mt < 2; ++mt)
            #pragma unroll
            for (int nt = 0; nt < 8; ++nt) {
                int code = c * 128 + nc * 64 + nt * 8 + (lane & 3) * 2;
                float en0 = s_en[code], en1 = s_en[code + 1];
                #pragma unroll
                for (int h = 0; h < 2; ++h) {
                    int l = mt * 2 + h;
                    float sc0 = fmaf(-2.0f, acc[mt][nt][h * 2],     en0);
                    float sc1 = fmaf(-2.0f, acc[mt][nt][h * 2 + 1], en1);
                    if (sc0 < b3[l]) {
                        if (sc0 < b1[l]) {
                            b3[l]=b2[l]; i3[l]=i2[l]; b2[l]=b1[l]; i2[l]=i1[l];
                            b1[l]=sc0;   i1[l]=code;
                        } else if (sc0 < b2[l]) {
                            b3[l]=b2[l]; i3[l]=i2[l]; b2[l]=sc0; i2[l]=code;
                        } else { b3[l]=sc0; i3[l]=code; }
                    }
                    if (sc1 < b3[l]) {
                        if (sc1 < b1[l]) {
                            b3[l]=b2[l]; i3[l]=i2[l]; b2[l]=b1[l]; i2[l]=i1[l];
                            b1[l]=sc1;   i1[l]=code + 1;
                        } else if (sc1 < b2[l]) {
                            b3[l]=b2[l]; i3[l]=i2[l]; b2[l]=sc1; i2[l]=code + 1;
                        } else { b3[l]=sc1; i3[l]=code + 1; }
                    }
                }
            }

        __syncthreads();
        if (c + 2 < 8) issue(c + 2);
    }

    // ---- row reduce over 8 partitions x top-3 ----
    __syncthreads();
    float* rb1 = (float*)(smem + SM_RED);
    float* rb2 = (float*)(smem + SM_RED + 4096);
    float* rb3 = (float*)(smem + SM_RED + 8192);
    int*   ri1 = (int*)  (smem + SM_RED + 12288);
    int*   ri2 = (int*)  (smem + SM_RED + 16384);
    int*   ri3 = (int*)  (smem + SM_RED + 20480);
    const int slot = nc * 4 + (lane & 3);
    #pragma unroll
    for (int l = 0; l < 4; ++l) {
        int R = mw * 32 + (l >> 1) * 16 + (l & 1) * 8 + (lane >> 2);
        rb1[R * 8 + slot] = b1[l]; ri1[R * 8 + slot] = i1[l];
        rb2[R * 8 + slot] = b2[l]; ri2[R * 8 + slot] = i2[l];
        rb3[R * 8 + slot] = b3[l]; ri3[R * 8 + slot] = i3[l];
    }
    if (tid == 0) s_cc = 0;
    __syncthreads();

    float lsum = 0.f;
    if (tid < 128) {
        float B1 = 3.4e38f, B2 = 3.4e38f;
        int I1 = 0x7fffffff;
        #pragma unroll
        for (int s = 0; s < 8; ++s) {
            int base = tid * 8 + s;
            float v; int iv;
            v = rb1[base]; iv = ri1[base];
            if (v < B1 || (v == B1 && iv < I1)) { B2 = B1; B1 = v; I1 = iv; }
            else if (v < B2) B2 = v;
            v = rb2[base]; iv = ri2[base];
            if (v < B1 || (v == B1 && iv < I1)) { B2 = B1; B1 = v; I1 = iv; }
            else if (v < B2) B2 = v;
            v = rb3[base]; iv = ri3[base];
            if (v < B1 || (v == B1 && iv < I1)) { B2 = B1; B1 = v; I1 = iv; }
            else if (v < B2) B2 = v;
        }
        s_idx[tid] = I1;
        lsum = B1;
        if (B2 - B1 < THETA) {
            int p = atomicAdd(&s_cc, 1);
            s_cnl[p] = tid;
        }
    }
    __syncthreads();

    // ---- in-CTA exact fix of contested rows (warp per row) ----
    // dist = fl(fl(zn - 2*dot) + enorm), zn double rounded once, strict-<
    // lowest-index tie-break; candidates = 24 entries from ri1/2/3.
    const int cc = s_cc;
    for (int j = warp; j < cc; j += 8) {
        const int R = s_cnl[j];
        const float* zr = z + (size_t)b * 262144 + hw0 + R;
        float zv[8];
        #pragma unroll
        for (int i = 0; i < 8; ++i)
            zv[i] = zr[(size_t)(lane + 32 * i) * 1024];
        double za = 0.0;
        #pragma unroll
        for (int i = 0; i < 8; ++i) za += (double)zv[i] * zv[i];
        #pragma unroll
        for (int o = 16; o; o >>= 1)
            za += __shfl_xor_sync(0xffffffffu, za, o);
        const float zn = (float)za;

        int kc24[24];
        #pragma unroll
        for (int s = 0; s < 8; ++s) {
            kc24[s * 3 + 0] = ri1[R * 8 + s];
            kc24[s * 3 + 1] = ri2[R * 8 + s];
            kc24[s * 3 + 2] = ri3[R * 8 + s];
        }

        float bd = 3.4e38f;
        int   bi = 0x7fffffff;
        #pragma unroll 1
        for (int jb = 0; jb < 24; jb += 4) {
            float ac[4] = {0.f, 0.f, 0.f, 0.f};
            #pragma unroll
            for (int i = 0; i < 8; ++i) {
                #pragma unroll
                for (int q = 0; q < 4; ++q)
                    ac[q] = fmaf(zv[i],
                                 E[(size_t)kc24[jb + q] * 256 + lane + 32 * i],
                                 ac[q]);
            }
            #pragma unroll
            for (int o = 16; o; o >>= 1) {
                #pragma unroll
                for (int q = 0; q < 4; ++q)
                    ac[q] += __shfl_xor_sync(0xffffffffu, ac[q], o);
            }
            #pragma unroll
            for (int q = 0; q < 4; ++q) {
                const int k = kc24[jb + q];
                float di = (zn - 2.0f * ac[q]) + g_enorm[k];
                if (di < bd || (di == bd && k < bi)) { bd = di; bi = k; }
            }
        }
        if (lane == 0) s_idx[R] = bi;
    }
    __syncthreads();

    // ---- indices out + counts ----
    if (tid < 128) {
        out[(size_t)OFF_IDX + n0 + tid] = (float)s_idx[tid];
        atomicAdd(&g_counts[s_idx[tid]], 1.0f);
    }

    // ---- stage 128 E rows (fp32) into smem (A/B regions are dead now) ----
    float* es = (float*)smem;                 // stride 260 floats per row
    for (int r = 0; r < 128; ++r)
        es[r * 260 + tid] = E[(size_t)s_idx[r] * 256 + tid];
    __syncthreads();

    // ---- gather/scatter for this CTA's 128 rows ----
    const float* zbg = z   + (size_t)b * 262144 + hw0;
    float*       qb  = out + (size_t)b * 262144 + hw0;
    float zs = 0.f;
    #pragma unroll 2
    for (int it = 0; it < 32; ++it) {
        int idx = tid + it * 256;             // 0..8191
        int nl  = idx & 127;                  // row in tile
        int d4  = idx >> 7;                   // 0..63
        int d   = d4 << 2;
        float4 e = *(const float4*)&es[nl * 260 + d];
        float z0 = zbg[(size_t)(d + 0) * 1024 + nl];
        float z1 = zbg[(size_t)(d + 1) * 1024 + nl];
        float z2 = zbg[(size_t)(d + 2) * 1024 + nl];
        float z3 = zbg[(size_t)(d + 3) * 1024 + nl];
        qb[(size_t)(d + 0) * 1024 + nl] = z0 + (e.x - z0);
        qb[(size_t)(d + 1) * 1024 + nl] = z1 + (e.y - z1);
        qb[(size_t)(d + 2) * 1024 + nl] = z2 + (e.z - z2);
        qb[(size_t)(d + 3) * 1024 + nl] = z3 + (e.w - z3);
        zs += z0 * z0 + z1 * z1 + z2 * z2 + z3 * z3;
        atomicAdd(&g_embed_sum4[(size_t)s_idx[nl] * 64 + d4],
                  make_float4(z0, z1, z2, z3));
    }

    // ---- loss partial: sum of best scores + sum of ||z||^2 ----
    float v = zs + lsum;
    #pragma unroll
    for (int o = 16; o; o >>= 1) v += __shfl_down_sync(0xffffffffu, v, o);
    if (lane == 0) ws2[warp] = v;
    __syncthreads();
    if (tid == 0) {
        float tot = 0.f;
        #pragma unroll
        for (int i = 0; i < 8; ++i) tot += ws2[i];
        atomicAdd(&g_loss, tot);
    }
}

// ---------------------------------------------------------------------------
// Kernel 3: merged EMA epilogue.
// ---------------------------------------------------------------------------
__global__ __launch_bounds__(1024)
void k_emb(const float* __restrict__ cs_in, const float* __restrict__ es_in,
           float* __restrict__ out) {
    __shared__ float s_n;
    const int tid = threadIdx.x;
    const int i = blockIdx.x * 1024 + tid;   // grid 256 -> 262144

    if (tid < 32) {
        float s = 0.f;
        #pragma unroll
        for (int j = 0; j < 32; ++j) s += cs_in[tid + j * 32];
        #pragma unroll
        for (int o = 16; o; o >>= 1) s += __shfl_xor_sync(0xffffffffu, s, o);
        if (tid == 0) s_n = 0.99f * s + 327.68f;
    }
    __syncthreads();

    const int k = i >> 8;
    float c = 0.99f * cs_in[k] + 0.01f * g_counts[k];
    if ((i & 255) == 0) out[(size_t)OFF_CS + k] = c;
    float n  = s_n;
    float cl = (c + 1e-5f) / (n + 0.01024f) * n;
    float es = 0.99f * es_in[i] + 0.01f * ((const float*)g_embed_sum4)[i];
    out[(size_t)OFF_ES  + i] = es;
    out[(size_t)OFF_EMB + i] = es / cl;
    if (i == 0)
        out[OFF_LOSS] = g_loss * (1.0f / 8388608.0f);
}

// ---------------------------------------------------------------------------
extern "C" void kernel_launch(void* const* d_in, const int* in_sizes, int n_in,
                              void* d_out, int out_size) {
    const float* z  = (const float*)d_in[0];
    const float* E  = (const float*)d_in[1];
    const float* cs = (const float*)d_in[2];
    const float* es = (const float*)d_in[3];
    float* out = (float*)d_out;

    cudaFuncSetAttribute(k_mma, cudaFuncAttributeMaxDynamicSharedMemorySize,
                         SMEM_MMA_TOTAL);

    k_init <<<1024, 256>>>(E, out);
    k_mma  <<< 256, 256, SMEM_MMA_TOTAL>>>(z, E, out);
    k_emb  <<< 256, 1024>>>(cs, es, out);
}

// round 12
// speedup vs baseline: 1.1824x; 1.1824x over previous
#include <cuda_runtime.h>
#include <cuda_fp16.h>
#include <cstdint>

// ---------------------------------------------------------------------------
// VQ-VAE vector quantizer, GB300 sm_103a (sm_103-generic toolchain).
// R10 structure with the exact-fix FUSED into k_mma (candidates stay in
// smem; k_fix kernel and g_cand/g_cn globals removed). Gather stays a
// separate high-occupancy kernel (R11 showed gather inside the occ-1 GEMM
// serializes: 153.7 -> 198.7).
// ---------------------------------------------------------------------------

#define N_ROWS   32768
#define K_CODES  1024
#define D_DIM    256

#define OFF_LOSS 8388608
#define OFF_IDX  8388609
#define OFF_EMB  8421377
#define OFF_CS   8683521
#define OFF_ES   8684545

#define THETA    2.5e-4f

__device__ float   g_enorm[K_CODES];
__device__ int     g_indices[N_ROWS];
__device__ float   g_counts[K_CODES];
__device__ float4  g_embed_sum4[K_CODES * 64];
__device__ __half  g_E16[K_CODES * D_DIM];
__device__ float   g_loss_sc;
__device__ float   g_loss_zn;

// ---------------- helpers --------------------------------------------------
__device__ __forceinline__ uint32_t smem_to_u32(const void* p) {
    uint32_t a;
    asm("{ .reg .u64 t; cvta.to.shared.u64 t, %1; cvt.u32.u64 %0, t; }"
        : "=r"(a) : "l"(p));
    return a;
}

__device__ __forceinline__ void ldm4(uint32_t r[4], uint32_t addr) {
    asm volatile("ldmatrix.sync.aligned.m8n8.x4.shared.b16 {%0,%1,%2,%3}, [%4];"
                 : "=r"(r[0]), "=r"(r[1]), "=r"(r[2]), "=r"(r[3]) : "r"(addr));
}

__device__ __forceinline__ void mma16816(float c[4], const uint32_t a[4],
                                         uint32_t b0, uint32_t b1) {
    asm volatile(
        "mma.sync.aligned.m16n8k16.row.col.f32.f16.f16.f32 "
        "{%0,%1,%2,%3}, {%4,%5,%6,%7}, {%8,%9}, {%0,%1,%2,%3};"
        : "+f"(c[0]), "+f"(c[1]), "+f"(c[2]), "+f"(c[3])
        : "r"(a[0]), "r"(a[1]), "r"(a[2]), "r"(a[3]), "r"(b0), "r"(b1));
}

// ---------------------------------------------------------------------------
// Kernel 1: ||e||^2, E -> fp16, zero scratch
// ---------------------------------------------------------------------------
__global__ void k_init(const float* __restrict__ E, float* __restrict__ out) {
    const int k = blockIdx.x;
    const int t = threadIdx.x;
    float v = E[k * D_DIM + t];
    g_E16[k * D_DIM + t] = __float2half_rn(v);
    float s = v * v;
    #pragma unroll
    for (int o = 16; o; o >>= 1) s += __shfl_down_sync(0xffffffffu, s, o);
    __shared__ float ws[8];
    if ((t & 31) == 0) ws[t >> 5] = s;
    __syncthreads();
    if (t == 0) {
        float tot = 0.f;
        #pragma unroll
        for (int i = 0; i < 8; ++i) tot += ws[i];
        g_enorm[k]  = tot;
        g_counts[k] = 0.f;
        if (k == 0) { g_loss_sc = 0.f; g_loss_zn = 0.f; }
    }
    ((float*)g_embed_sum4)[k * 256 + t] = 0.f;
}

// ---------------------------------------------------------------------------
// Kernel 2: fp16 mma.sync GEMM (128 rows/CTA x 1024 codes, D=256)
// + in-CTA exact fix of contested rows (candidates stay in smem).
// Chunk order: mma -> fold -> sync -> issue(c+2). (R7/R8: moving the fold
// after issue spills acc; do not reorder.)
// ---------------------------------------------------------------------------
#define SM_A   0
#define SM_B   65536
#define SM_EN  196608
#define SM_RED SM_B
#define SMEM_MMA_TOTAL 200704

__global__ __launch_bounds__(256, 1)
void k_mma(const float* __restrict__ z, const float* __restrict__ E,
           float* __restrict__ out) {
    extern __shared__ char smem[];
    __shared__ int   s_idx[128];
    __shared__ int   s_cnl[128];
    __shared__ int   s_cc;
    __shared__ float lws[8];
    const uint32_t sb = smem_to_u32(smem);
    const int tid  = threadIdx.x;
    const int warp = tid >> 5;
    const int lane = tid & 31;
    const int n0  = blockIdx.x * 128;
    const int b   = n0 >> 10;
    const int hw0 = n0 & 1023;

    // ---- prologue: A tile (z rows -> fp16, swizzled row-major [row][d]) ----
    const float4* zb4 = (const float4*)(z + (size_t)b * 262144 + hw0);
    #pragma unroll 4
    for (int i = 0; i < 16; ++i) {
        int f  = i * 256 + tid;
        int d2 = f >> 5;
        int r4 = f & 31;
        float4 v0 = zb4[(2 * d2) * 256 + r4];
        float4 v1 = zb4[(2 * d2 + 1) * 256 + r4];
        float a0[4] = {v0.x, v0.y, v0.z, v0.w};
        float a1[4] = {v1.x, v1.y, v1.z, v1.w};
        #pragma unroll
        for (int j = 0; j < 4; ++j) {
            int row = r4 * 4 + j;
            uint32_t off = ((uint32_t)row << 9) | ((uint32_t)d2 << 2);
            off ^= (uint32_t)(row & 7) << 4;
            *(__half2*)(smem + off) = __floats2half2_rn(a0[j], a1[j]);
        }
    }
    float* s_en = (float*)(smem + SM_EN);
    #pragma unroll
    for (int i = 0; i < 4; ++i) s_en[tid + i * 256] = g_enorm[tid + i * 256];

    auto issue = [&](int c) {
        const __half* src = g_E16 + (size_t)c * 128 * 256;
        const uint32_t base = sb + SM_B + (uint32_t)(c & 1) * 65536;
        #pragma unroll
        for (int i = 0; i < 16; ++i) {
            int lin  = tid + i * 256;
            int code = lin >> 5, d8 = lin & 31;
            uint32_t off = ((uint32_t)code << 9) + ((uint32_t)d8 << 4);
            off ^= (uint32_t)(code & 7) << 4;
            const void* g = src + code * 256 + d8 * 8;
            asm volatile("cp.async.cg.shared.global [%0], [%1], 16;"
                         :: "r"(base + off), "l"(g));
        }
        asm volatile("cp.async.commit_group;" ::: "memory");
    };
    issue(0);
    issue(1);
    __syncthreads();

    const int mw = warp & 3;
    const int nc = warp >> 2;
    const int mat = lane >> 3, rwi = lane & 7;

    uint32_t aBase[2], aXor[2];
    #pragma unroll
    for (int mt = 0; mt < 2; ++mt) {
        int row = mw * 32 + mt * 16 + rwi + ((mat & 1) << 3);
        aBase[mt] = sb + ((uint32_t)row << 9);
        aXor[mt]  = (uint32_t)(row & 7) << 4;
    }
    const uint32_t aK = (uint32_t)(mat >> 1) << 4;

    uint32_t bBase[4], bXor[4];
    #pragma unroll
    for (int np = 0; np < 4; ++np) {
        int code = nc * 64 + np * 16 + rwi + ((mat >> 1) << 3);
        bBase[np] = ((uint32_t)code << 9);
        bXor[np]  = (uint32_t)(code & 7) << 4;
    }
    const uint32_t bK = (uint32_t)(mat & 1) << 4;

    float b1[4], b2[4], b3[4];
    int   i1[4], i2[4], i3[4];
    #pragma unroll
    for (int l = 0; l < 4; ++l) {
        b1[l] = b2[l] = b3[l] = 3.4e38f;
        i1[l] = i2[l] = i3[l] = 0;
    }

    for (int c = 0; c < 8; ++c) {
        if (c == 7) asm volatile("cp.async.wait_group 0;" ::: "memory");
        else        asm volatile("cp.async.wait_group 1;" ::: "memory");
        __syncthreads();

        const uint32_t bBuf = sb + SM_B + (uint32_t)(c & 1) * 65536;
        float acc[2][8][4];
        #pragma unroll
        for (int mt = 0; mt < 2; ++mt)
            #pragma unroll
            for (int nt = 0; nt < 8; ++nt)
                #pragma unroll
                for (int q = 0; q < 4; ++q) acc[mt][nt][q] = 0.f;

        #pragma unroll 2
        for (int ks = 0; ks < 16; ++ks) {
            const uint32_t kb = (uint32_t)ks << 5;
            uint32_t af[2][4], bf[4][4];
            #pragma unroll
            for (int mt = 0; mt < 2; ++mt)
                ldm4(af[mt], aBase[mt] + ((kb + aK) ^ aXor[mt]));
            #pragma unroll
            for (int np = 0; np < 4; ++np)
                ldm4(bf[np], bBuf + bBase[np] + ((kb + bK) ^ bXor[np]));
            #pragma unroll
            for (int mt = 0; mt < 2; ++mt)
                #pragma unroll
                for (int np = 0; np < 4; ++np) {
                    mma16816(acc[mt][np * 2],     af[mt], bf[np][0], bf[np][1]);
                    mma16816(acc[mt][np * 2 + 1], af[mt], bf[np][2], bf[np][3]);
                }
        }

        // fold FIRST (consumes acc), then sync, then refill buffer
        #pragma unroll
        for (int mt = 0; mt < 2; ++mt)
            #pragma unroll
            for (int nt = 0; nt < 8; ++nt) {
                int code = c * 128 + nc * 64 + nt * 8 + (lane & 3) * 2;
                float en0 = s_en[code], en1 = s_en[code + 1];
                #pragma unroll
                for (int h = 0; h < 2; ++h) {
                    int l = mt * 2 + h;
                    float sc0 = fmaf(-2.0f, acc[mt][nt][h * 2],     en0);
                    float sc1 = fmaf(-2.0f, acc[mt][nt][h * 2 + 1], en1);
                    if (sc0 < b3[l]) {
                        if (sc0 < b1[l]) {
                            b3[l]=b2[l]; i3[l]=i2[l]; b2[l]=b1[l]; i2[l]=i1[l];
                            b1[l]=sc0;   i1[l]=code;
                        } else if (sc0 < b2[l]) {
                            b3[l]=b2[l]; i3[l]=i2[l]; b2[l]=sc0; i2[l]=code;
                        } else { b3[l]=sc0; i3[l]=code; }
                    }
                    if (sc1 < b3[l]) {
                        if (sc1 < b1[l]) {
                            b3[l]=b2[l]; i3[l]=i2[l]; b2[l]=b1[l]; i2[l]=i1[l];
                            b1[l]=sc1;   i1[l]=code + 1;
                        } else if (sc1 < b2[l]) {
                            b3[l]=b2[l]; i3[l]=i2[l]; b2[l]=sc1; i2[l]=code + 1;
                        } else { b3[l]=sc1; i3[l]=code + 1; }
                    }
                }
            }

        __syncthreads();
        if (c + 2 < 8) issue(c + 2);
    }

    // ---- row reduce over 8 partitions x top-3 ----
    __syncthreads();
    float* rb1 = (float*)(smem + SM_RED);
    float* rb2 = (float*)(smem + SM_RED + 4096);
    float* rb3 = (float*)(smem + SM_RED + 8192);
    int*   ri1 = (int*)  (smem + SM_RED + 12288);
    int*   ri2 = (int*)  (smem + SM_RED + 16384);
    int*   ri3 = (int*)  (smem + SM_RED + 20480);
    const int slot = nc * 4 + (lane & 3);
    #pragma unroll
    for (int l = 0; l < 4; ++l) {
        int R = mw * 32 + (l >> 1) * 16 + (l & 1) * 8 + (lane >> 2);
        rb1[R * 8 + slot] = b1[l]; ri1[R * 8 + slot] = i1[l];
        rb2[R * 8 + slot] = b2[l]; ri2[R * 8 + slot] = i2[l];
        rb3[R * 8 + slot] = b3[l]; ri3[R * 8 + slot] = i3[l];
    }
    if (tid == 0) s_cc = 0;
    __syncthreads();

    float lsum = 0.f;
    if (tid < 128) {
        float B1 = 3.4e38f, B2 = 3.4e38f;
        int I1 = 0x7fffffff;
        #pragma unroll
        for (int s = 0; s < 8; ++s) {
            int base = tid * 8 + s;
            float v; int iv;
            v = rb1[base]; iv = ri1[base];
            if (v < B1 || (v == B1 && iv < I1)) { B2 = B1; B1 = v; I1 = iv; }
            else if (v < B2) B2 = v;
            v = rb2[base]; iv = ri2[base];
            if (v < B1 || (v == B1 && iv < I1)) { B2 = B1; B1 = v; I1 = iv; }
            else if (v < B2) B2 = v;
            v = rb3[base]; iv = ri3[base];
            if (v < B1 || (v == B1 && iv < I1)) { B2 = B1; B1 = v; I1 = iv; }
            else if (v < B2) B2 = v;
        }
        s_idx[tid] = I1;
        lsum = B1;
        if (B2 - B1 < THETA) {
            int p = atomicAdd(&s_cc, 1);
            s_cnl[p] = tid;
        }
    }
    __syncthreads();

    // ---- in-CTA exact fix of contested rows (warp per row, smem cands) ----
    const int cc = s_cc;
    for (int j = warp; j < cc; j += 8) {
        const int R = s_cnl[j];
        const float* zr = z + (size_t)b * 262144 + hw0 + R;
        float zv[8];
        #pragma unroll
        for (int i = 0; i < 8; ++i)
            zv[i] = zr[(size_t)(lane + 32 * i) * 1024];
        double za = 0.0;
        #pragma unroll
        for (int i = 0; i < 8; ++i) za += (double)zv[i] * zv[i];
        #pragma unroll
        for (int o = 16; o; o >>= 1)
            za += __shfl_xor_sync(0xffffffffu, za, o);
        const float zn = (float)za;

        int kc24[24];
        #pragma unroll
        for (int s = 0; s < 8; ++s) {
            kc24[s * 3 + 0] = ri1[R * 8 + s];
            kc24[s * 3 + 1] = ri2[R * 8 + s];
            kc24[s * 3 + 2] = ri3[R * 8 + s];
        }

        float bd = 3.4e38f;
        int   bi = 0x7fffffff;
        #pragma unroll 1
        for (int jb = 0; jb < 24; jb += 4) {
            float ac[4] = {0.f, 0.f, 0.f, 0.f};
            #pragma unroll
            for (int i = 0; i < 8; ++i) {
                #pragma unroll
                for (int q = 0; q < 4; ++q)
                    ac[q] = fmaf(zv[i],
                                 E[(size_t)kc24[jb + q] * 256 + lane + 32 * i],
                                 ac[q]);
            }
            #pragma unroll
            for (int o = 16; o; o >>= 1) {
                #pragma unroll
                for (int q = 0; q < 4; ++q)
                    ac[q] += __shfl_xor_sync(0xffffffffu, ac[q], o);
            }
            #pragma unroll
            for (int q = 0; q < 4; ++q) {
                const int k = kc24[jb + q];
                float di = (zn - 2.0f * ac[q]) + g_enorm[k];
                if (di < bd || (di == bd && k < bi)) { bd = di; bi = k; }
            }
        }
        if (lane == 0) s_idx[R] = bi;
    }
    __syncthreads();

    // ---- final indices out ----
    if (tid < 128) {
        const int n = n0 + tid;
        g_indices[n] = s_idx[tid];
        out[(size_t)OFF_IDX + n] = (float)s_idx[tid];
    }

    // ---- loss partial (best scores) ----
    #pragma unroll
    for (int o = 16; o; o >>= 1) lsum += __shfl_down_sync(0xffffffffu, lsum, o);
    if (lane == 0) lws[warp] = lsum;
    __syncthreads();
    if (tid == 0) {
        float tot = 0.f;
        #pragma unroll
        for (int i = 0; i < 8; ++i) tot += lws[i];
        atomicAdd(&g_loss_sc, tot);
    }
}

// ---------------------------------------------------------------------------
// Kernel 3: fused gather/scatter (high-occupancy; R10 version).
// z_q_st = fl(z + fl(E[idx]-z)), ||z||^2 partial, float4 RED scatter, counts.
// ---------------------------------------------------------------------------
__global__ __launch_bounds__(256)
void k_gather(const float* __restrict__ z, const float* __restrict__ E,
              float* __restrict__ out) {
    __shared__ float es[32 * 260];
    __shared__ int   sidx[32];
    __shared__ float ws[8];
    const int t   = threadIdx.x;
    const int n0  = blockIdx.x * 32;     // grid 1024
    const int b   = n0 >> 10;
    const int rem = n0 & 1023;

    if (t < 32) {
        int k = g_indices[n0 + t];
        sidx[t] = k;
        atomicAdd(&g_counts[k], 1.0f);
    }
    __syncthreads();

    #pragma unroll
    for (int k = 0; k < 32; ++k)
        es[k * 260 + t] = E[(size_t)sidx[k] * 256 + t];
    __syncthreads();

    const float* zb = z   + (size_t)b * 262144 + rem;
    float*       qb = out + (size_t)b * 262144 + rem;

    float zs = 0.f;
    #pragma unroll 2
    for (int it = 0; it < 8; ++it) {
        int idx = t + it * 256;          // 0..2047
        int nl  = idx & 31;
        int d4  = idx >> 5;              // 0..63
        int d   = d4 << 2;
        float4 e = *(const float4*)&es[nl * 260 + d];
        float z0 = zb[(size_t)(d + 0) * 1024 + nl];
        float z1 = zb[(size_t)(d + 1) * 1024 + nl];
        float z2 = zb[(size_t)(d + 2) * 1024 + nl];
        float z3 = zb[(size_t)(d + 3) * 1024 + nl];
        qb[(size_t)(d + 0) * 1024 + nl] = z0 + (e.x - z0);
        qb[(size_t)(d + 1) * 1024 + nl] = z1 + (e.y - z1);
        qb[(size_t)(d + 2) * 1024 + nl] = z2 + (e.z - z2);
        qb[(size_t)(d + 3) * 1024 + nl] = z3 + (e.w - z3);
        zs += z0 * z0 + z1 * z1 + z2 * z2 + z3 * z3;
        atomicAdd(&g_embed_sum4[(size_t)sidx[nl] * 64 + d4],
                  make_float4(z0, z1, z2, z3));
    }
    #pragma unroll
    for (int o = 16; o; o >>= 1) zs += __shfl_down_sync(0xffffffffu, zs, o);
    if ((t & 31) == 0) ws[t >> 5] = zs;
    __syncthreads();
    if (t == 0) {
        float tot = 0.f;
        #pragma unroll
        for (int i = 0; i < 8; ++i) tot += ws[i];
        atomicAdd(&g_loss_zn, tot);
    }
}

// ---------------------------------------------------------------------------
// Kernel 4: merged EMA epilogue.
// ---------------------------------------------------------------------------
__global__ __launch_bounds__(1024)
void k_emb(const float* __restrict__ cs_in, const float* __restrict__ es_in,
           float* __restrict__ out) {
    __shared__ float s_n;
    const int tid = threadIdx.x;
    const int i = blockIdx.x * 1024 + tid;   // grid 256 -> 262144

    if (tid < 32) {
        float s = 0.f;
        #pragma unroll
        for (int j = 0; j < 32; ++j) s += cs_in[tid + j * 32];
        #pragma unroll
        for (int o = 16; o; o >>= 1) s += __shfl_xor_sync(0xffffffffu, s, o);
        if (tid == 0) s_n = 0.99f * s + 327.68f;
    }
    __syncthreads();

    const int k = i >> 8;
    float c = 0.99f * cs_in[k] + 0.01f * g_counts[k];
    if ((i & 255) == 0) out[(size_t)OFF_CS + k] = c;
    float n  = s_n;
    float cl = (c + 1e-5f) / (n + 0.01024f) * n;
    float es = 0.99f * es_in[i] + 0.01f * ((const float*)g_embed_sum4)[i];
    out[(size_t)OFF_ES  + i] = es;
    out[(size_t)OFF_EMB + i] = es / cl;
    if (i == 0)
        out[OFF_LOSS] = (g_loss_zn + g_loss_sc) * (1.0f / 8388608.0f);
}

// ---------------------------------------------------------------------------
extern "C" void kernel_launch(void* const* d_in, const int* in_sizes, int n_in,
                              void* d_out, int out_size) {
    const float* z  = (const float*)d_in[0];
    const float* E  = (const float*)d_in[1];
    const float* cs = (const float*)d_in[2];
    const float* es = (const float*)d_in[3];
    float* out = (float*)d_out;

    cudaFuncSetAttribute(k_mma, cudaFuncAttributeMaxDynamicSharedMemorySize,
                         SMEM_MMA_TOTAL);

    k_init  <<<1024, 256>>>(E, out);
    k_mma   <<< 256, 256, SMEM_MMA_TOTAL>>>(z, E, out);
    k_gather<<<1024, 256>>>(z, E, out);
    k_emb   <<< 256, 1024>>>(cs, es, out);
}

// round 14
// speedup vs baseline: 1.2256x; 1.0365x over previous
#include <cuda_runtime.h>
#include <cuda_fp16.h>
#include <cstdint>

// ---------------------------------------------------------------------------
// VQ-VAE vector quantizer, GB300 sm_103a (sm_103-generic toolchain).
// R12 structure, k_mma re-tiled to 64 rows/CTA (100KB smem -> 2 CTAs/SM:
// sibling CTA's MMA hides the serial fold that occ-1 exposed).
// Candidate partitions unchanged: 8 partitions x 128 codes, top-3 each.
// ---------------------------------------------------------------------------

#define N_ROWS   32768
#define K_CODES  1024
#define D_DIM    256

#define OFF_LOSS 8388608
#define OFF_IDX  8388609
#define OFF_EMB  8421377
#define OFF_CS   8683521
#define OFF_ES   8684545

#define THETA    2.5e-4f

__device__ float   g_enorm[K_CODES];
__device__ int     g_indices[N_ROWS];
__device__ float   g_counts[K_CODES];
__device__ float4  g_embed_sum4[K_CODES * 64];
__device__ __half  g_E16[K_CODES * D_DIM];
__device__ float   g_loss_sc;
__device__ float   g_loss_zn;

// ---------------- helpers --------------------------------------------------
__device__ __forceinline__ uint32_t smem_to_u32(const void* p) {
    uint32_t a;
    asm("{ .reg .u64 t; cvta.to.shared.u64 t, %1; cvt.u32.u64 %0, t; }"
        : "=r"(a) : "l"(p));
    return a;
}

__device__ __forceinline__ void ldm4(uint32_t r[4], uint32_t addr) {
    asm volatile("ldmatrix.sync.aligned.m8n8.x4.shared.b16 {%0,%1,%2,%3}, [%4];"
                 : "=r"(r[0]), "=r"(r[1]), "=r"(r[2]), "=r"(r[3]) : "r"(addr));
}

__device__ __forceinline__ void mma16816(float c[4], const uint32_t a[4],
                                         uint32_t b0, uint32_t b1) {
    asm volatile(
        "mma.sync.aligned.m16n8k16.row.col.f32.f16.f16.f32 "
        "{%0,%1,%2,%3}, {%4,%5,%6,%7}, {%8,%9}, {%0,%1,%2,%3};"
        : "+f"(c[0]), "+f"(c[1]), "+f"(c[2]), "+f"(c[3])
        : "r"(a[0]), "r"(a[1]), "r"(a[2]), "r"(a[3]), "r"(b0), "r"(b1));
}

// ---------------------------------------------------------------------------
// Kernel 1: ||e||^2, E -> fp16, zero scratch
// ---------------------------------------------------------------------------
__global__ void k_init(const float* __restrict__ E, float* __restrict__ out) {
    const int k = blockIdx.x;
    const int t = threadIdx.x;
    float v = E[k * D_DIM + t];
    g_E16[k * D_DIM + t] = __float2half_rn(v);
    float s = v * v;
    #pragma unroll
    for (int o = 16; o; o >>= 1) s += __shfl_down_sync(0xffffffffu, s, o);
    __shared__ float ws[8];
    if ((t & 31) == 0) ws[t >> 5] = s;
    __syncthreads();
    if (t == 0) {
        float tot = 0.f;
        #pragma unroll
        for (int i = 0; i < 8; ++i) tot += ws[i];
        g_enorm[k]  = tot;
        g_counts[k] = 0.f;
        if (k == 0) { g_loss_sc = 0.f; g_loss_zn = 0.f; }
    }
    ((float*)g_embed_sum4)[k * 256 + t] = 0.f;
}

// ---------------------------------------------------------------------------
// Kernel 2: fp16 mma.sync GEMM, 64 rows/CTA x 1024 codes, D=256, 2 CTAs/SM.
// 8 warps: 4(m, 16 rows each) x 2(n, 32 codes each of 64-code chunks).
// 16 chunks of 64 codes, double-buffered cp.async.
// Per-thread top-3 per row-slot over its 128-code partition (8 partitions).
// Chunk order: mma -> fold -> sync -> issue(c+2). (fold must precede issue.)
// + in-CTA exact fix of contested rows.
// ---------------------------------------------------------------------------
#define SM_A   0
#define SM_B   32768
#define SM_EN  98304
#define SM_RED SM_B
#define SMEM_MMA_TOTAL 102400

__global__ __launch_bounds__(256, 2)
void k_mma(const float* __restrict__ z, const float* __restrict__ E,
           float* __restrict__ out) {
    extern __shared__ char smem[];
    __shared__ int   s_idx[64];
    __shared__ int   s_cnl[64];
    __shared__ int   s_cc;
    __shared__ float lws[8];
    const uint32_t sb = smem_to_u32(smem);
    const int tid  = threadIdx.x;
    const int warp = tid >> 5;
    const int lane = tid & 31;
    const int n0  = blockIdx.x * 64;     // grid 512
    const int b   = n0 >> 10;
    const int hw0 = n0 & 1023;

    // ---- prologue: A tile (64 z rows -> fp16, swizzled [row][d]) ----
    const float4* zb4 = (const float4*)(z + (size_t)b * 262144 + hw0);
    #pragma unroll 4
    for (int i = 0; i < 8; ++i) {
        int f  = i * 256 + tid;
        int d2 = f >> 4;           // 0..127 (d-pair)
        int r4 = f & 15;           // 16 float4 = 64 rows
        float4 v0 = zb4[(2 * d2) * 256 + r4];
        float4 v1 = zb4[(2 * d2 + 1) * 256 + r4];
        float a0[4] = {v0.x, v0.y, v0.z, v0.w};
        float a1[4] = {v1.x, v1.y, v1.z, v1.w};
        #pragma unroll
        for (int j = 0; j < 4; ++j) {
            int row = r4 * 4 + j;
            uint32_t off = ((uint32_t)row << 9) | ((uint32_t)d2 << 2);
            off ^= (uint32_t)(row & 7) << 4;
            *(__half2*)(smem + off) = __floats2half2_rn(a0[j], a1[j]);
        }
    }
    float* s_en = (float*)(smem + SM_EN);
    #pragma unroll
    for (int i = 0; i < 4; ++i) s_en[tid + i * 256] = g_enorm[tid + i * 256];

    auto issue = [&](int c) {
        const __half* src = g_E16 + (size_t)c * 64 * 256;
        const uint32_t base = sb + SM_B + (uint32_t)(c & 1) * 32768;
        #pragma unroll
        for (int i = 0; i < 8; ++i) {
            int lin  = tid + i * 256;
            int code = lin >> 5, d8 = lin & 31;
            uint32_t off = ((uint32_t)code << 9) + ((uint32_t)d8 << 4);
            off ^= (uint32_t)(code & 7) << 4;
            const void* g = src + code * 256 + d8 * 8;
            asm volatile("cp.async.cg.shared.global [%0], [%1], 16;"
                         :: "r"(base + off), "l"(g));
        }
        asm volatile("cp.async.commit_group;" ::: "memory");
    };
    issue(0);
    issue(1);
    __syncthreads();

    const int mw = warp & 3;        // rows mw*16 .. mw*16+15
    const int nc = warp >> 2;       // codes nc*32 within 64-code chunk
    const int mat = lane >> 3, rwi = lane & 7;

    const int arow = mw * 16 + rwi + ((mat & 1) << 3);
    const uint32_t aBase = sb + ((uint32_t)arow << 9);
    const uint32_t aXor  = (uint32_t)(arow & 7) << 4;
    const uint32_t aK    = (uint32_t)(mat >> 1) << 4;

    uint32_t bBase[2], bXor[2];
    #pragma unroll
    for (int np = 0; np < 2; ++np) {
        int code = nc * 32 + np * 16 + rwi + ((mat >> 1) << 3);
        bBase[np] = ((uint32_t)code << 9);
        bXor[np]  = (uint32_t)(code & 7) << 4;
    }
    const uint32_t bK = (uint32_t)(mat & 1) << 4;

    float b1[2], b2[2], b3[2];
    int   i1[2], i2[2], i3[2];
    #pragma unroll
    for (int l = 0; l < 2; ++l) {
        b1[l] = b2[l] = b3[l] = 3.4e38f;
        i1[l] = i2[l] = i3[l] = 0;
    }

    for (int c = 0; c < 16; ++c) {
        if (c == 15) asm volatile("cp.async.wait_group 0;" ::: "memory");
        else         asm volatile("cp.async.wait_group 1;" ::: "memory");
        __syncthreads();

        const uint32_t bBuf = sb + SM_B + (uint32_t)(c & 1) * 32768;
        float acc[4][4];
        #pragma unroll
        for (int nt = 0; nt < 4; ++nt)
            #pragma unroll
            for (int q = 0; q < 4; ++q) acc[nt][q] = 0.f;

        #pragma unroll 2
        for (int ks = 0; ks < 16; ++ks) {
            const uint32_t kb = (uint32_t)ks << 5;
            uint32_t af[4], bf[2][4];
            ldm4(af, aBase + ((kb + aK) ^ aXor));
            #pragma unroll
            for (int np = 0; np < 2; ++np)
                ldm4(bf[np], bBuf + bBase[np] + ((kb + bK) ^ bXor[np]));
            #pragma unroll
            for (int np = 0; np < 2; ++np) {
                mma16816(acc[np * 2],     af, bf[np][0], bf[np][1]);
                mma16816(acc[np * 2 + 1], af, bf[np][2], bf[np][3]);
            }
        }

        // fold FIRST (consumes acc), then sync, then refill buffer
        #pragma unroll
        for (int nt = 0; nt < 4; ++nt) {
            int code = c * 64 + nc * 32 + nt * 8 + (lane & 3) * 2;
            float en0 = s_en[code], en1 = s_en[code + 1];
            #pragma unroll
            for (int h = 0; h < 2; ++h) {     // h=0: row lane>>2, h=1: +8
                float sc0 = fmaf(-2.0f, acc[nt][h * 2],     en0);
                float sc1 = fmaf(-2.0f, acc[nt][h * 2 + 1], en1);
                if (sc0 < b3[h]) {
                    if (sc0 < b1[h]) {
                        b3[h]=b2[h]; i3[h]=i2[h]; b2[h]=b1[h]; i2[h]=i1[h];
                        b1[h]=sc0;   i1[h]=code;
                    } else if (sc0 < b2[h]) {
                        b3[h]=b2[h]; i3[h]=i2[h]; b2[h]=sc0; i2[h]=code;
                    } else { b3[h]=sc0; i3[h]=code; }
                }
                if (sc1 < b3[h]) {
                    if (sc1 < b1[h]) {
                        b3[h]=b2[h]; i3[h]=i2[h]; b2[h]=b1[h]; i2[h]=i1[h];
                        b1[h]=sc1;   i1[h]=code + 1;
                    } else if (sc1 < b2[h]) {
                        b3[h]=b2[h]; i3[h]=i2[h]; b2[h]=sc1; i2[h]=code + 1;
                    } else { b3[h]=sc1; i3[h]=code + 1; }
                }
            }
        }

        __syncthreads();
        if (c + 2 < 16) issue(c + 2);
    }

    // ---- row reduce over 8 partitions x top-3 (64 rows) ----
    __syncthreads();
    float* rb1 = (float*)(smem + SM_RED);
    float* rb2 = (float*)(smem + SM_RED + 2048);
    float* rb3 = (float*)(smem + SM_RED + 4096);
    int*   ri1 = (int*)  (smem + SM_RED + 6144);
    int*   ri2 = (int*)  (smem + SM_RED + 8192);
    int*   ri3 = (int*)  (smem + SM_RED + 10240);
    const int slot = nc * 4 + (lane & 3);
    #pragma unroll
    for (int l = 0; l < 2; ++l) {
        int R = mw * 16 + l * 8 + (lane >> 2);
        rb1[R * 8 + slot] = b1[l]; ri1[R * 8 + slot] = i1[l];
        rb2[R * 8 + slot] = b2[l]; ri2[R * 8 + slot] = i2[l];
        rb3[R * 8 + slot] = b3[l]; ri3[R * 8 + slot] = i3[l];
    }
    if (tid == 0) s_cc = 0;
    __syncthreads();

    float lsum = 0.f;
    if (tid < 64) {
        float B1 = 3.4e38f, B2 = 3.4e38f;
        int I1 = 0x7fffffff;
        #pragma unroll
        for (int s = 0; s < 8; ++s) {
            int base = tid * 8 + s;
            float v; int iv;
            v = rb1[base]; iv = ri1[base];
            if (v < B1 || (v == B1 && iv < I1)) { B2 = B1; B1 = v; I1 = iv; }
            else if (v < B2) B2 = v;
            v = rb2[base]; iv = ri2[base];
            if (v < B1 || (v == B1 && iv < I1)) { B2 = B1; B1 = v; I1 = iv; }
            else if (v < B2) B2 = v;
            v = rb3[base]; iv = ri3[base];
            if (v < B1 || (v == B1 && iv < I1)) { B2 = B1; B1 = v; I1 = iv; }
            else if (v < B2) B2 = v;
        }
        s_idx[tid] = I1;
        lsum = B1;
        if (B2 - B1 < THETA) {
            int p = atomicAdd(&s_cc, 1);
            s_cnl[p] = tid;
        }
    }
    __syncthreads();

    // ---- in-CTA exact fix of contested rows (warp per row, smem cands) ----
    const int cc = s_cc;
    for (int j = warp; j < cc; j += 8) {
        const int R = s_cnl[j];
        const float* zr = z + (size_t)b * 262144 + hw0 + R;
        float zv[8];
        #pragma unroll
        for (int i = 0; i < 8; ++i)
            zv[i] = zr[(size_t)(lane + 32 * i) * 1024];
        double za = 0.0;
        #pragma unroll
        for (int i = 0; i < 8; ++i) za += (double)zv[i] * zv[i];
        #pragma unroll
        for (int o = 16; o; o >>= 1)
            za += __shfl_xor_sync(0xffffffffu, za, o);
        const float zn = (float)za;

        int kc24[24];
        #pragma unroll
        for (int s = 0; s < 8; ++s) {
            kc24[s * 3 + 0] = ri1[R * 8 + s];
            kc24[s * 3 + 1] = ri2[R * 8 + s];
            kc24[s * 3 + 2] = ri3[R * 8 + s];
        }

        float bd = 3.4e38f;
        int   bi = 0x7fffffff;
        #pragma unroll 1
        for (int jb = 0; jb < 24; jb += 4) {
            float ac[4] = {0.f, 0.f, 0.f, 0.f};
            #pragma unroll
            for (int i = 0; i < 8; ++i) {
                #pragma unroll
                for (int q = 0; q < 4; ++q)
                    ac[q] = fmaf(zv[i],
                                 E[(size_t)kc24[jb + q] * 256 + lane + 32 * i],
                                 ac[q]);
            }
            #pragma unroll
            for (int o = 16; o; o >>= 1) {
                #pragma unroll
                for (int q = 0; q < 4; ++q)
                    ac[q] += __shfl_xor_sync(0xffffffffu, ac[q], o);
            }
            #pragma unroll
            for (int q = 0; q < 4; ++q) {
                const int k = kc24[jb + q];
                float di = (zn - 2.0f * ac[q]) + g_enorm[k];
                if (di < bd || (di == bd && k < bi)) { bd = di; bi = k; }
            }
        }
        if (lane == 0) s_idx[R] = bi;
    }
    __syncthreads();

    // ---- final indices out ----
    if (tid < 64) {
        const int n = n0 + tid;
        g_indices[n] = s_idx[tid];
        out[(size_t)OFF_IDX + n] = (float)s_idx[tid];
    }

    // ---- loss partial (best scores) ----
    #pragma unroll
    for (int o = 16; o; o >>= 1) lsum += __shfl_down_sync(0xffffffffu, lsum, o);
    if (lane == 0) lws[warp] = lsum;
    __syncthreads();
    if (tid == 0) {
        float tot = 0.f;
        #pragma unroll
        for (int i = 0; i < 8; ++i) tot += lws[i];
        atomicAdd(&g_loss_sc, tot);
    }
}

// ---------------------------------------------------------------------------
// Kernel 3: fused gather/scatter (high-occupancy).
// z_q_st = fl(z + fl(E[idx]-z)), ||z||^2 partial, float4 RED scatter, counts.
// ---------------------------------------------------------------------------
__global__ __launch_bounds__(256)
void k_gather(const float* __restrict__ z, const float* __restrict__ E,
              float* __restrict__ out) {
    __shared__ float es[32 * 260];
    __shared__ int   sidx[32];
    __shared__ float ws[8];
    const int t   = threadIdx.x;
    const int n0  = blockIdx.x * 32;     // grid 1024
    const int b   = n0 >> 10;
    const int rem = n0 & 1023;

    if (t < 32) {
        int k = g_indices[n0 + t];
        sidx[t] = k;
        atomicAdd(&g_counts[k], 1.0f);
    }
    __syncthreads();

    #pragma unroll
    for (int k = 0; k < 32; ++k)
        es[k * 260 + t] = E[(size_t)sidx[k] * 256 + t];
    __syncthreads();

    const float* zb = z   + (size_t)b * 262144 + rem;
    float*       qb = out + (size_t)b * 262144 + rem;

    float zs = 0.f;
    #pragma unroll 2
    for (int it = 0; it < 8; ++it) {
        int idx = t + it * 256;          // 0..2047
        int nl  = idx & 31;
        int d4  = idx >> 5;              // 0..63
        int d   = d4 << 2;
        float4 e = *(const float4*)&es[nl * 260 + d];
        float z0 = zb[(size_t)(d + 0) * 1024 + nl];
        float z1 = zb[(size_t)(d + 1) * 1024 + nl];
        float z2 = zb[(size_t)(d + 2) * 1024 + nl];
        float z3 = zb[(size_t)(d + 3) * 1024 + nl];
        qb[(size_t)(d + 0) * 1024 + nl] = z0 + (e.x - z0);
        qb[(size_t)(d + 1) * 1024 + nl] = z1 + (e.y - z1);
        qb[(size_t)(d + 2) * 1024 + nl] = z2 + (e.z - z2);
        qb[(size_t)(d + 3) * 1024 + nl] = z3 + (e.w - z3);
        zs += z0 * z0 + z1 * z1 + z2 * z2 + z3 * z3;
        atomicAdd(&g_embed_sum4[(size_t)sidx[nl] * 64 + d4],
                  make_float4(z0, z1, z2, z3));
    }
    #pragma unroll
    for (int o = 16; o; o >>= 1) zs += __shfl_down_sync(0xffffffffu, zs, o);
    if ((t & 31) == 0) ws[t >> 5] = zs;
    __syncthreads();
    if (t == 0) {
        float tot = 0.f;
        #pragma unroll
        for (int i = 0; i < 8; ++i) tot += ws[i];
        atomicAdd(&g_loss_zn, tot);
    }
}

// ---------------------------------------------------------------------------
// Kernel 4: merged EMA epilogue.
// ---------------------------------------------------------------------------
__global__ __launch_bounds__(1024)
void k_emb(const float* __restrict__ cs_in, const float* __restrict__ es_in,
           float* __restrict__ out) {
    __shared__ float s_n;
    const int tid = threadIdx.x;
    const int i = blockIdx.x * 1024 + tid;   // grid 256 -> 262144

    if (tid < 32) {
        float s = 0.f;
        #pragma unroll
        for (int j = 0; j < 32; ++j) s += cs_in[tid + j * 32];
        #pragma unroll
        for (int o = 16; o; o >>= 1) s += __shfl_xor_sync(0xffffffffu, s, o);
        if (tid == 0) s_n = 0.99f * s + 327.68f;
    }
    __syncthreads();

    const int k = i >> 8;
    float c = 0.99f * cs_in[k] + 0.01f * g_counts[k];
    if ((i & 255) == 0) out[(size_t)OFF_CS + k] = c;
    float n  = s_n;
    float cl = (c + 1e-5f) / (n + 0.01024f) * n;
    float es = 0.99f * es_in[i] + 0.01f * ((const float*)g_embed_sum4)[i];
    out[(size_t)OFF_ES  + i] = es;
    out[(size_t)OFF_EMB + i] = es / cl;
    if (i == 0)
        out[OFF_LOSS] = (g_loss_zn + g_loss_sc) * (1.0f / 8388608.0f);
}

// ---------------------------------------------------------------------------
extern "C" void kernel_launch(void* const* d_in, const int* in_sizes, int n_in,
                              void* d_out, int out_size) {
    const float* z  = (const float*)d_in[0];
    const float* E  = (const float*)d_in[1];
    const float* cs = (const float*)d_in[2];
    const float* es = (const float*)d_in[3];
    float* out = (float*)d_out;

    cudaFuncSetAttribute(k_mma, cudaFuncAttributeMaxDynamicSharedMemorySize,
                         SMEM_MMA_TOTAL);

    k_init  <<<1024, 256>>>(E, out);
    k_mma   <<< 512, 256, SMEM_MMA_TOTAL>>>(z, E, out);
    k_gather<<<1024, 256>>>(z, E, out);
    k_emb   <<< 256, 1024>>>(cs, es, out);
}

// round 15
// speedup vs baseline: 1.3281x; 1.0836x over previous
#include <cuda_runtime.h>
#include <cuda_fp16.h>
#include <cstdint>

// ---------------------------------------------------------------------------
// VQ-VAE vector quantizer, GB300 sm_103a (sm_103-generic toolchain).
// k_mma: 128 rows/CTA (B traffic stays 128MB, 256 CTAs = SINGLE wave at
// 2 CTAs/SM) with 32-code B chunks (A 64KB + B 2x16KB + en 4KB = 100KB).
// R14 lesson: halving rows doubles B traffic — shrink the B chunk instead.
// Candidate partitions invariant: 8 partitions x 128 codes, top-3 each.
// ---------------------------------------------------------------------------

#define N_ROWS   32768
#define K_CODES  1024
#define D_DIM    256

#define OFF_LOSS 8388608
#define OFF_IDX  8388609
#define OFF_EMB  8421377
#define OFF_CS   8683521
#define OFF_ES   8684545

#define THETA    2.5e-4f

__device__ float   g_enorm[K_CODES];
__device__ int     g_indices[N_ROWS];
__device__ float   g_counts[K_CODES];
__device__ float4  g_embed_sum4[K_CODES * 64];
__device__ __half  g_E16[K_CODES * D_DIM];
__device__ float   g_loss_sc;
__device__ float   g_loss_zn;

// ---------------- helpers --------------------------------------------------
__device__ __forceinline__ uint32_t smem_to_u32(const void* p) {
    uint32_t a;
    asm("{ .reg .u64 t; cvta.to.shared.u64 t, %1; cvt.u32.u64 %0, t; }"
        : "=r"(a) : "l"(p));
    return a;
}

__device__ __forceinline__ void ldm4(uint32_t r[4], uint32_t addr) {
    asm volatile("ldmatrix.sync.aligned.m8n8.x4.shared.b16 {%0,%1,%2,%3}, [%4];"
                 : "=r"(r[0]), "=r"(r[1]), "=r"(r[2]), "=r"(r[3]) : "r"(addr));
}

__device__ __forceinline__ void mma16816(float c[4], const uint32_t a[4],
                                         uint32_t b0, uint32_t b1) {
    asm volatile(
        "mma.sync.aligned.m16n8k16.row.col.f32.f16.f16.f32 "
        "{%0,%1,%2,%3}, {%4,%5,%6,%7}, {%8,%9}, {%0,%1,%2,%3};"
        : "+f"(c[0]), "+f"(c[1]), "+f"(c[2]), "+f"(c[3])
        : "r"(a[0]), "r"(a[1]), "r"(a[2]), "r"(a[3]), "r"(b0), "r"(b1));
}

// ---------------------------------------------------------------------------
// Kernel 1: ||e||^2, E -> fp16, zero scratch
// ---------------------------------------------------------------------------
__global__ void k_init(const float* __restrict__ E, float* __restrict__ out) {
    const int k = blockIdx.x;
    const int t = threadIdx.x;
    float v = E[k * D_DIM + t];
    g_E16[k * D_DIM + t] = __float2half_rn(v);
    float s = v * v;
    #pragma unroll
    for (int o = 16; o; o >>= 1) s += __shfl_down_sync(0xffffffffu, s, o);
    __shared__ float ws[8];
    if ((t & 31) == 0) ws[t >> 5] = s;
    __syncthreads();
    if (t == 0) {
        float tot = 0.f;
        #pragma unroll
        for (int i = 0; i < 8; ++i) tot += ws[i];
        g_enorm[k]  = tot;
        g_counts[k] = 0.f;
        if (k == 0) { g_loss_sc = 0.f; g_loss_zn = 0.f; }
    }
    ((float*)g_embed_sum4)[k * 256 + t] = 0.f;
}

// ---------------------------------------------------------------------------
// Kernel 2: fp16 mma.sync GEMM, 128 rows/CTA x 1024 codes, 2 CTAs/SM.
// 32 chunks of 32 codes, double-buffered. 8 warps: 4(m:32 rows)x2(n:16 codes).
// Chunk order: mma -> fold -> sync -> issue(c+2) (fold must precede issue).
// + in-CTA exact fix of contested rows.
// ---------------------------------------------------------------------------
#define SM_A   0
#define SM_B   65536
#define SM_EN  98304
#define SM_RED SM_B
#define SMEM_MMA_TOTAL 102400

__global__ __launch_bounds__(256, 2)
void k_mma(const float* __restrict__ z, const float* __restrict__ E,
           float* __restrict__ out) {
    extern __shared__ char smem[];
    __shared__ int   s_idx[128];
    __shared__ int   s_cnl[128];
    __shared__ int   s_cc;
    __shared__ float lws[8];
    const uint32_t sb = smem_to_u32(smem);
    const int tid  = threadIdx.x;
    const int warp = tid >> 5;
    const int lane = tid & 31;
    const int n0  = blockIdx.x * 128;    // grid 256
    const int b   = n0 >> 10;
    const int hw0 = n0 & 1023;

    // ---- prologue: A tile (128 z rows -> fp16, swizzled [row][d]) ----
    const float4* zb4 = (const float4*)(z + (size_t)b * 262144 + hw0);
    #pragma unroll 4
    for (int i = 0; i < 16; ++i) {
        int f  = i * 256 + tid;
        int d2 = f >> 5;
        int r4 = f & 31;
        float4 v0 = zb4[(2 * d2) * 256 + r4];
        float4 v1 = zb4[(2 * d2 + 1) * 256 + r4];
        float a0[4] = {v0.x, v0.y, v0.z, v0.w};
        float a1[4] = {v1.x, v1.y, v1.z, v1.w};
        #pragma unroll
        for (int j = 0; j < 4; ++j) {
            int row = r4 * 4 + j;
            uint32_t off = ((uint32_t)row << 9) | ((uint32_t)d2 << 2);
            off ^= (uint32_t)(row & 7) << 4;
            *(__half2*)(smem + off) = __floats2half2_rn(a0[j], a1[j]);
        }
    }
    float* s_en = (float*)(smem + SM_EN);
    #pragma unroll
    for (int i = 0; i < 4; ++i) s_en[tid + i * 256] = g_enorm[tid + i * 256];

    // chunk c = codes [c*32, c*32+32), 16KB, buffer (c&1)
    auto issue = [&](int c) {
        const __half* src = g_E16 + (size_t)c * 32 * 256;
        const uint32_t base = sb + SM_B + (uint32_t)(c & 1) * 16384;
        #pragma unroll
        for (int i = 0; i < 4; ++i) {
            int lin  = tid + i * 256;
            int code = lin >> 5, d8 = lin & 31;
            uint32_t off = ((uint32_t)code << 9) + ((uint32_t)d8 << 4);
            off ^= (uint32_t)(code & 7) << 4;
            const void* g = src + code * 256 + d8 * 8;
            asm volatile("cp.async.cg.shared.global [%0], [%1], 16;"
                         :: "r"(base + off), "l"(g));
        }
        asm volatile("cp.async.commit_group;" ::: "memory");
    };
    issue(0);
    issue(1);
    __syncthreads();

    const int mw = warp & 3;        // rows mw*32 .. +31
    const int nc = warp >> 2;       // codes nc*16 within 32-code chunk
    const int mat = lane >> 3, rwi = lane & 7;

    uint32_t aBase[2], aXor[2];
    #pragma unroll
    for (int mt = 0; mt < 2; ++mt) {
        int row = mw * 32 + mt * 16 + rwi + ((mat & 1) << 3);
        aBase[mt] = sb + ((uint32_t)row << 9);
        aXor[mt]  = (uint32_t)(row & 7) << 4;
    }
    const uint32_t aK = (uint32_t)(mat >> 1) << 4;

    const int bcode = nc * 16 + rwi + ((mat >> 1) << 3);
    const uint32_t bBase = ((uint32_t)bcode << 9);
    const uint32_t bXor  = (uint32_t)(bcode & 7) << 4;
    const uint32_t bK    = (uint32_t)(mat & 1) << 4;

    float b1[4], b2[4], b3[4];
    int   i1[4], i2[4], i3[4];
    #pragma unroll
    for (int l = 0; l < 4; ++l) {
        b1[l] = b2[l] = b3[l] = 3.4e38f;
        i1[l] = i2[l] = i3[l] = 0;
    }

    for (int c = 0; c < 32; ++c) {
        if (c == 31) asm volatile("cp.async.wait_group 0;" ::: "memory");
        else         asm volatile("cp.async.wait_group 1;" ::: "memory");
        __syncthreads();

        const uint32_t bBuf = sb + SM_B + (uint32_t)(c & 1) * 16384;
        float acc[2][2][4];
        #pragma unroll
        for (int mt = 0; mt < 2; ++mt)
            #pragma unroll
            for (int nt = 0; nt < 2; ++nt)
                #pragma unroll
                for (int q = 0; q < 4; ++q) acc[mt][nt][q] = 0.f;

        #pragma unroll 4
        for (int ks = 0; ks < 16; ++ks) {
            const uint32_t kb = (uint32_t)ks << 5;
            uint32_t af[2][4], bf[4];
            #pragma unroll
            for (int mt = 0; mt < 2; ++mt)
                ldm4(af[mt], aBase[mt] + ((kb + aK) ^ aXor[mt]));
            ldm4(bf, bBuf + bBase + ((kb + bK) ^ bXor));
            #pragma unroll
            for (int mt = 0; mt < 2; ++mt) {
                mma16816(acc[mt][0], af[mt], bf[0], bf[1]);
                mma16816(acc[mt][1], af[mt], bf[2], bf[3]);
            }
        }

        // fold FIRST (consumes acc), then sync, then refill buffer
        #pragma unroll
        for (int mt = 0; mt < 2; ++mt)
            #pragma unroll
            for (int nt = 0; nt < 2; ++nt) {
                int code = c * 32 + nc * 16 + nt * 8 + (lane & 3) * 2;
                float en0 = s_en[code], en1 = s_en[code + 1];
                #pragma unroll
                for (int h = 0; h < 2; ++h) {
                    int l = mt * 2 + h;
                    float sc0 = fmaf(-2.0f, acc[mt][nt][h * 2],     en0);
                    float sc1 = fmaf(-2.0f, acc[mt][nt][h * 2 + 1], en1);
                    if (sc0 < b3[l]) {
                        if (sc0 < b1[l]) {
                            b3[l]=b2[l]; i3[l]=i2[l]; b2[l]=b1[l]; i2[l]=i1[l];
                            b1[l]=sc0;   i1[l]=code;
                        } else if (sc0 < b2[l]) {
                            b3[l]=b2[l]; i3[l]=i2[l]; b2[l]=sc0; i2[l]=code;
                        } else { b3[l]=sc0; i3[l]=code; }
                    }
                    if (sc1 < b3[l]) {
                        if (sc1 < b1[l]) {
                            b3[l]=b2[l]; i3[l]=i2[l]; b2[l]=b1[l]; i2[l]=i1[l];
                            b1[l]=sc1;   i1[l]=code + 1;
                        } else if (sc1 < b2[l]) {
                            b3[l]=b2[l]; i3[l]=i2[l]; b2[l]=sc1; i2[l]=code + 1;
                        } else { b3[l]=sc1; i3[l]=code + 1; }
                    }
                }
            }

        __syncthreads();
        if (c + 2 < 32) issue(c + 2);
    }

    // ---- row reduce over 8 partitions x top-3 (128 rows) ----
    __syncthreads();
    float* rb1 = (float*)(smem + SM_RED);
    float* rb2 = (float*)(smem + SM_RED + 4096);
    float* rb3 = (float*)(smem + SM_RED + 8192);
    int*   ri1 = (int*)  (smem + SM_RED + 12288);
    int*   ri2 = (int*)  (smem + SM_RED + 16384);
    int*   ri3 = (int*)  (smem + SM_RED + 20480);
    const int slot = nc * 4 + (lane & 3);
    #pragma unroll
    for (int l = 0; l < 4; ++l) {
        int R = mw * 32 + (l >> 1) * 16 + (l & 1) * 8 + (lane >> 2);
        rb1[R * 8 + slot] = b1[l]; ri1[R * 8 + slot] = i1[l];
        rb2[R * 8 + slot] = b2[l]; ri2[R * 8 + slot] = i2[l];
        rb3[R * 8 + slot] = b3[l]; ri3[R * 8 + slot] = i3[l];
    }
    if (tid == 0) s_cc = 0;
    __syncthreads();

    float lsum = 0.f;
    if (tid < 128) {
        float B1 = 3.4e38f, B2 = 3.4e38f;
        int I1 = 0x7fffffff;
        #pragma unroll
        for (int s = 0; s < 8; ++s) {
            int base = tid * 8 + s;
            float v; int iv;
            v = rb1[base]; iv = ri1[base];
            if (v < B1 || (v == B1 && iv < I1)) { B2 = B1; B1 = v; I1 = iv; }
            else if (v < B2) B2 = v;
            v = rb2[base]; iv = ri2[base];
            if (v < B1 || (v == B1 && iv < I1)) { B2 = B1; B1 = v; I1 = iv; }
            else if (v < B2) B2 = v;
            v = rb3[base]; iv = ri3[base];
            if (v < B1 || (v == B1 && iv < I1)) { B2 = B1; B1 = v; I1 = iv; }
            else if (v < B2) B2 = v;
        }
        s_idx[tid] = I1;
        lsum = B1;
        if (B2 - B1 < THETA) {
            int p = atomicAdd(&s_cc, 1);
            s_cnl[p] = tid;
        }
    }
    __syncthreads();

    // ---- in-CTA exact fix of contested rows (warp per row, smem cands) ----
    const int cc = s_cc;
    for (int j = warp; j < cc; j += 8) {
        const int R = s_cnl[j];
        const float* zr = z + (size_t)b * 262144 + hw0 + R;
        float zv[8];
        #pragma unroll
        for (int i = 0; i < 8; ++i)
            zv[i] = zr[(size_t)(lane + 32 * i) * 1024];
        double za = 0.0;
        #pragma unroll
        for (int i = 0; i < 8; ++i) za += (double)zv[i] * zv[i];
        #pragma unroll
        for (int o = 16; o; o >>= 1)
            za += __shfl_xor_sync(0xffffffffu, za, o);
        const float zn = (float)za;

        int kc24[24];
        #pragma unroll
        for (int s = 0; s < 8; ++s) {
            kc24[s * 3 + 0] = ri1[R * 8 + s];
            kc24[s * 3 + 1] = ri2[R * 8 + s];
            kc24[s * 3 + 2] = ri3[R * 8 + s];
        }

        float bd = 3.4e38f;
        int   bi = 0x7fffffff;
        #pragma unroll 1
        for (int jb = 0; jb < 24; jb += 4) {
            float ac[4] = {0.f, 0.f, 0.f, 0.f};
            #pragma unroll
            for (int i = 0; i < 8; ++i) {
                #pragma unroll
                for (int q = 0; q < 4; ++q)
                    ac[q] = fmaf(zv[i],
                                 E[(size_t)kc24[jb + q] * 256 + lane + 32 * i],
                                 ac[q]);
            }
            #pragma unroll
            for (int o = 16; o; o >>= 1) {
                #pragma unroll
                for (int q = 0; q < 4; ++q)
                    ac[q] += __shfl_xor_sync(0xffffffffu, ac[q], o);
            }
            #pragma unroll
            for (int q = 0; q < 4; ++q) {
                const int k = kc24[jb + q];
                float di = (zn - 2.0f * ac[q]) + g_enorm[k];
                if (di < bd || (di == bd && k < bi)) { bd = di; bi = k; }
            }
        }
        if (lane == 0) s_idx[R] = bi;
    }
    __syncthreads();

    // ---- final indices out ----
    if (tid < 128) {
        const int n = n0 + tid;
        g_indices[n] = s_idx[tid];
        out[(size_t)OFF_IDX + n] = (float)s_idx[tid];
    }

    // ---- loss partial (best scores) ----
    #pragma unroll
    for (int o = 16; o; o >>= 1) lsum += __shfl_down_sync(0xffffffffu, lsum, o);
    if (lane == 0) lws[warp] = lsum;
    __syncthreads();
    if (tid == 0) {
        float tot = 0.f;
        #pragma unroll
        for (int i = 0; i < 8; ++i) tot += lws[i];
        atomicAdd(&g_loss_sc, tot);
    }
}

// ---------------------------------------------------------------------------
// Kernel 3: fused gather/scatter (high-occupancy).
// z_q_st = fl(z + fl(E[idx]-z)), ||z||^2 partial, float4 RED scatter, counts.
// ---------------------------------------------------------------------------
__global__ __launch_bounds__(256)
void k_gather(const float* __restrict__ z, const float* __restrict__ E,
              float* __restrict__ out) {
    __shared__ float es[32 * 260];
    __shared__ int   sidx[32];
    __shared__ float ws[8];
    const int t   = threadIdx.x;
    const int n0  = blockIdx.x * 32;     // grid 1024
    const int b   = n0 >> 10;
    const int rem = n0 & 1023;

    if (t < 32) {
        int k = g_indices[n0 + t];
        sidx[t] = k;
        atomicAdd(&g_counts[k], 1.0f);
    }
    __syncthreads();

    #pragma unroll
    for (int k = 0; k < 32; ++k)
        es[k * 260 + t] = E[(size_t)sidx[k] * 256 + t];
    __syncthreads();

    const float* zb = z   + (size_t)b * 262144 + rem;
    float*       qb = out + (size_t)b * 262144 + rem;

    float zs = 0.f;
    #pragma unroll 2
    for (int it = 0; it < 8; ++it) {
        int idx = t + it * 256;          // 0..2047
        int nl  = idx & 31;
        int d4  = idx >> 5;              // 0..63
        int d   = d4 << 2;
        float4 e = *(const float4*)&es[nl * 260 + d];
        float z0 = zb[(size_t)(d + 0) * 1024 + nl];
        float z1 = zb[(size_t)(d + 1) * 1024 + nl];
        float z2 = zb[(size_t)(d + 2) * 1024 + nl];
        float z3 = zb[(size_t)(d + 3) * 1024 + nl];
        qb[(size_t)(d + 0) * 1024 + nl] = z0 + (e.x - z0);
        qb[(size_t)(d + 1) * 1024 + nl] = z1 + (e.y - z1);
        qb[(size_t)(d + 2) * 1024 + nl] = z2 + (e.z - z2);
        qb[(size_t)(d + 3) * 1024 + nl] = z3 + (e.w - z3);
        zs += z0 * z0 + z1 * z1 + z2 * z2 + z3 * z3;
        atomicAdd(&g_embed_sum4[(size_t)sidx[nl] * 64 + d4],
                  make_float4(z0, z1, z2, z3));
    }
    #pragma unroll
    for (int o = 16; o; o >>= 1) zs += __shfl_down_sync(0xffffffffu, zs, o);
    if ((t & 31) == 0) ws[t >> 5] = zs;
    __syncthreads();
    if (t == 0) {
        float tot = 0.f;
        #pragma unroll
        for (int i = 0; i < 8; ++i) tot += ws[i];
        atomicAdd(&g_loss_zn, tot);
    }
}

// ---------------------------------------------------------------------------
// Kernel 4: merged EMA epilogue.
// ---------------------------------------------------------------------------
__global__ __launch_bounds__(1024)
void k_emb(const float* __restrict__ cs_in, const float* __restrict__ es_in,
           float* __restrict__ out) {
    __shared__ float s_n;
    const int tid = threadIdx.x;
    const int i = blockIdx.x * 1024 + tid;   // grid 256 -> 262144

    if (tid < 32) {
        float s = 0.f;
        #pragma unroll
        for (int j = 0; j < 32; ++j) s += cs_in[tid + j * 32];
        #pragma unroll
        for (int o = 16; o; o >>= 1) s += __shfl_xor_sync(0xffffffffu, s, o);
        if (tid == 0) s_n = 0.99f * s + 327.68f;
    }
    __syncthreads();

    const int k = i >> 8;
    float c = 0.99f * cs_in[k] + 0.01f * g_counts[k];
    if ((i & 255) == 0) out[(size_t)OFF_CS + k] = c;
    float n  = s_n;
    float cl = (c + 1e-5f) / (n + 0.01024f) * n;
    float es = 0.99f * es_in[i] + 0.01f * ((const float*)g_embed_sum4)[i];
    out[(size_t)OFF_ES  + i] = es;
    out[(size_t)OFF_EMB + i] = es / cl;
    if (i == 0)
        out[OFF_LOSS] = (g_loss_zn + g_loss_sc) * (1.0f / 8388608.0f);
}

// ---------------------------------------------------------------------------
extern "C" void kernel_launch(void* const* d_in, const int* in_sizes, int n_in,
                              void* d_out, int out_size) {
    const float* z  = (const float*)d_in[0];
    const float* E  = (const float*)d_in[1];
    const float* cs = (const float*)d_in[2];
    const float* es = (const float*)d_in[3];
    float* out = (float*)d_out;

    cudaFuncSetAttribute(k_mma, cudaFuncAttributeMaxDynamicSharedMemorySize,
                         SMEM_MMA_TOTAL);

    k_init  <<<1024, 256>>>(E, out);
    k_mma   <<< 256, 256, SMEM_MMA_TOTAL>>>(z, E, out);
    k_gather<<<1024, 256>>>(z, E, out);
    k_emb   <<< 256, 1024>>>(cs, es, out);
}

// round 16
// speedup vs baseline: 1.4463x; 1.0890x over previous
#include <cuda_runtime.h>
#include <cuda_fp16.h>
#include <cstdint>

// ---------------------------------------------------------------------------
// VQ-VAE vector quantizer, GB300 sm_103a (sm_103-generic toolchain).
// k_mma: 128 rows/CTA, 16 chunks x 64 codes, SINGLE 32KB B buffer
// (A 64KB + B 32KB + en 4KB = 100KB -> 2 CTAs/SM, single wave).
// Warp tile 32x32 (4 ldsm : 8 mma — halves LDSM vs R15's 32x16 tile).
// cp.async latency hidden by the sibling CTA (cross-CTA pipelining).
// Candidate partitions invariant: 8 partitions x 128 codes, top-3 each.
// ||z||^2 loss partial moved into k_mma's fp32 prologue (off k_gather).
// ---------------------------------------------------------------------------

#define N_ROWS   32768
#define K_CODES  1024
#define D_DIM    256

#define OFF_LOSS 8388608
#define OFF_IDX  8388609
#define OFF_EMB  8421377
#define OFF_CS   8683521
#define OFF_ES   8684545

#define THETA    2.5e-4f

__device__ float   g_enorm[K_CODES];
__device__ int     g_indices[N_ROWS];
__device__ float   g_counts[K_CODES];
__device__ float4  g_embed_sum4[K_CODES * 64];
__device__ __half  g_E16[K_CODES * D_DIM];
__device__ float   g_loss_sc;
__device__ float   g_loss_zn;

// ---------------- helpers --------------------------------------------------
__device__ __forceinline__ uint32_t smem_to_u32(const void* p) {
    uint32_t a;
    asm("{ .reg .u64 t; cvta.to.shared.u64 t, %1; cvt.u32.u64 %0, t; }"
        : "=r"(a) : "l"(p));
    return a;
}

__device__ __forceinline__ void ldm4(uint32_t r[4], uint32_t addr) {
    asm volatile("ldmatrix.sync.aligned.m8n8.x4.shared.b16 {%0,%1,%2,%3}, [%4];"
                 : "=r"(r[0]), "=r"(r[1]), "=r"(r[2]), "=r"(r[3]) : "r"(addr));
}

__device__ __forceinline__ void mma16816(float c[4], const uint32_t a[4],
                                         uint32_t b0, uint32_t b1) {
    asm volatile(
        "mma.sync.aligned.m16n8k16.row.col.f32.f16.f16.f32 "
        "{%0,%1,%2,%3}, {%4,%5,%6,%7}, {%8,%9}, {%0,%1,%2,%3};"
        : "+f"(c[0]), "+f"(c[1]), "+f"(c[2]), "+f"(c[3])
        : "r"(a[0]), "r"(a[1]), "r"(a[2]), "r"(a[3]), "r"(b0), "r"(b1));
}

// ---------------------------------------------------------------------------
// Kernel 1: ||e||^2, E -> fp16, zero scratch
// ---------------------------------------------------------------------------
__global__ void k_init(const float* __restrict__ E, float* __restrict__ out) {
    const int k = blockIdx.x;
    const int t = threadIdx.x;
    float v = E[k * D_DIM + t];
    g_E16[k * D_DIM + t] = __float2half_rn(v);
    float s = v * v;
    #pragma unroll
    for (int o = 16; o; o >>= 1) s += __shfl_down_sync(0xffffffffu, s, o);
    __shared__ float ws[8];
    if ((t & 31) == 0) ws[t >> 5] = s;
    __syncthreads();
    if (t == 0) {
        float tot = 0.f;
        #pragma unroll
        for (int i = 0; i < 8; ++i) tot += ws[i];
        g_enorm[k]  = tot;
        g_counts[k] = 0.f;
        if (k == 0) { g_loss_sc = 0.f; g_loss_zn = 0.f; }
    }
    ((float*)g_embed_sum4)[k * 256 + t] = 0.f;
}

// ---------------------------------------------------------------------------
// Kernel 2: fp16 mma.sync GEMM, 128 rows/CTA x 1024 codes, 2 CTAs/SM.
// 16 chunks of 64 codes, single 32KB buffer. 8 warps: 4(m:32)x2(n:32).
// Chunk order: wait -> sync -> mma -> fold -> sync -> issue(c+1).
// (fold must precede issue: R7/R8 register lesson.)
// + in-CTA exact fix of contested rows.
// ---------------------------------------------------------------------------
#define SM_A   0
#define SM_B   65536
#define SM_EN  98304
#define SM_RED SM_B
#define SMEM_MMA_TOTAL 102400

__global__ __launch_bounds__(256, 2)
void k_mma(const float* __restrict__ z, const float* __restrict__ E,
           float* __restrict__ out) {
    extern __shared__ char smem[];
    __shared__ int   s_idx[128];
    __shared__ int   s_cnl[128];
    __shared__ int   s_cc;
    __shared__ float lws[8];
    const uint32_t sb = smem_to_u32(smem);
    const int tid  = threadIdx.x;
    const int warp = tid >> 5;
    const int lane = tid & 31;
    const int n0  = blockIdx.x * 128;    // grid 256
    const int b   = n0 >> 10;
    const int hw0 = n0 & 1023;

    // ---- prologue: A tile (128 z rows -> fp16, swizzled [row][d]) ----
    // also accumulates the ||z||^2 loss partial from the fp32 values.
    float zs = 0.f;
    const float4* zb4 = (const float4*)(z + (size_t)b * 262144 + hw0);
    #pragma unroll 4
    for (int i = 0; i < 16; ++i) {
        int f  = i * 256 + tid;
        int d2 = f >> 5;
        int r4 = f & 31;
        float4 v0 = zb4[(2 * d2) * 256 + r4];
        float4 v1 = zb4[(2 * d2 + 1) * 256 + r4];
        zs += v0.x * v0.x + v0.y * v0.y + v0.z * v0.z + v0.w * v0.w
            + v1.x * v1.x + v1.y * v1.y + v1.z * v1.z + v1.w * v1.w;
        float a0[4] = {v0.x, v0.y, v0.z, v0.w};
        float a1[4] = {v1.x, v1.y, v1.z, v1.w};
        #pragma unroll
        for (int j = 0; j < 4; ++j) {
            int row = r4 * 4 + j;
            uint32_t off = ((uint32_t)row << 9) | ((uint32_t)d2 << 2);
            off ^= (uint32_t)(row & 7) << 4;
            *(__half2*)(smem + off) = __floats2half2_rn(a0[j], a1[j]);
        }
    }
    float* s_en = (float*)(smem + SM_EN);
    #pragma unroll
    for (int i = 0; i < 4; ++i) s_en[tid + i * 256] = g_enorm[tid + i * 256];

    // chunk c = codes [c*64, c*64+64), 32KB, single buffer
    auto issue = [&](int c) {
        const __half* src = g_E16 + (size_t)c * 64 * 256;
        const uint32_t base = sb + SM_B;
        #pragma unroll
        for (int i = 0; i < 8; ++i) {
            int lin  = tid + i * 256;
            int code = lin >> 5, d8 = lin & 31;
            uint32_t off = ((uint32_t)code << 9) + ((uint32_t)d8 << 4);
            off ^= (uint32_t)(code & 7) << 4;
            const void* g = src + code * 256 + d8 * 8;
            asm volatile("cp.async.cg.shared.global [%0], [%1], 16;"
                         :: "r"(base + off), "l"(g));
        }
        asm volatile("cp.async.commit_group;" ::: "memory");
    };
    issue(0);
    __syncthreads();

    const int mw = warp & 3;        // rows mw*32 .. +31
    const int nc = warp >> 2;       // codes nc*32 within 64-code chunk
    const int mat = lane >> 3, rwi = lane & 7;

    uint32_t aBase[2], aXor[2];
    #pragma unroll
    for (int mt = 0; mt < 2; ++mt) {
        int row = mw * 32 + mt * 16 + rwi + ((mat & 1) << 3);
        aBase[mt] = sb + ((uint32_t)row << 9);
        aXor[mt]  = (uint32_t)(row & 7) << 4;
    }
    const uint32_t aK = (uint32_t)(mat >> 1) << 4;

    uint32_t bBase[2], bXor[2];
    #pragma unroll
    for (int np = 0; np < 2; ++np) {
        int code = nc * 32 + np * 16 + rwi + ((mat >> 1) << 3);
        bBase[np] = ((uint32_t)code << 9);
        bXor[np]  = (uint32_t)(code & 7) << 4;
    }
    const uint32_t bK = (uint32_t)(mat & 1) << 4;

    float b1[4], b2[4], b3[4];
    int   i1[4], i2[4], i3[4];
    #pragma unroll
    for (int l = 0; l < 4; ++l) {
        b1[l] = b2[l] = b3[l] = 3.4e38f;
        i1[l] = i2[l] = i3[l] = 0;
    }

    const uint32_t bBuf = sb + SM_B;
    for (int c = 0; c < 16; ++c) {
        asm volatile("cp.async.wait_group 0;" ::: "memory");
        __syncthreads();

        float acc[2][4][4];
        #pragma unroll
        for (int mt = 0; mt < 2; ++mt)
            #pragma unroll
            for (int nt = 0; nt < 4; ++nt)
                #pragma unroll
                for (int q = 0; q < 4; ++q) acc[mt][nt][q] = 0.f;

        #pragma unroll 2
        for (int ks = 0; ks < 16; ++ks) {
            const uint32_t kb = (uint32_t)ks << 5;
            uint32_t af[2][4], bf[2][4];
            #pragma unroll
            for (int mt = 0; mt < 2; ++mt)
                ldm4(af[mt], aBase[mt] + ((kb + aK) ^ aXor[mt]));
            #pragma unroll
            for (int np = 0; np < 2; ++np)
                ldm4(bf[np], bBuf + bBase[np] + ((kb + bK) ^ bXor[np]));
            #pragma unroll
            for (int mt = 0; mt < 2; ++mt)
                #pragma unroll
                for (int np = 0; np < 2; ++np) {
                    mma16816(acc[mt][np * 2],     af[mt], bf[np][0], bf[np][1]);
                    mma16816(acc[mt][np * 2 + 1], af[mt], bf[np][2], bf[np][3]);
                }
        }

        // fold FIRST (consumes acc), then sync, then refill buffer
        #pragma unroll
        for (int mt = 0; mt < 2; ++mt)
            #pragma unroll
            for (int nt = 0; nt < 4; ++nt) {
                int code = c * 64 + nc * 32 + nt * 8 + (lane & 3) * 2;
                float en0 = s_en[code], en1 = s_en[code + 1];
                #pragma unroll
                for (int h = 0; h < 2; ++h) {
                    int l = mt * 2 + h;
                    float sc0 = fmaf(-2.0f, acc[mt][nt][h * 2],     en0);
                    float sc1 = fmaf(-2.0f, acc[mt][nt][h * 2 + 1], en1);
                    if (sc0 < b3[l]) {
                        if (sc0 < b1[l]) {
                            b3[l]=b2[l]; i3[l]=i2[l]; b2[l]=b1[l]; i2[l]=i1[l];
                            b1[l]=sc0;   i1[l]=code;
                        } else if (sc0 < b2[l]) {
                            b3[l]=b2[l]; i3[l]=i2[l]; b2[l]=sc0; i2[l]=code;
                        } else { b3[l]=sc0; i3[l]=code; }
                    }
                    if (sc1 < b3[l]) {
                        if (sc1 < b1[l]) {
                            b3[l]=b2[l]; i3[l]=i2[l]; b2[l]=b1[l]; i2[l]=i1[l];
                            b1[l]=sc1;   i1[l]=code + 1;
                        } else if (sc1 < b2[l]) {
                            b3[l]=b2[l]; i3[l]=i2[l]; b2[l]=sc1; i2[l]=code + 1;
                        } else { b3[l]=sc1; i3[l]=code + 1; }
                    }
                }
            }

        __syncthreads();
        if (c + 1 < 16) issue(c + 1);
    }

    // ---- row reduce over 8 partitions x top-3 (128 rows) ----
    __syncthreads();
    float* rb1 = (float*)(smem + SM_RED);
    float* rb2 = (float*)(smem + SM_RED + 4096);
    float* rb3 = (float*)(smem + SM_RED + 8192);
    int*   ri1 = (int*)  (smem + SM_RED + 12288);
    int*   ri2 = (int*)  (smem + SM_RED + 16384);
    int*   ri3 = (int*)  (smem + SM_RED + 20480);
    const int slot = nc * 4 + (lane & 3);
    #pragma unroll
    for (int l = 0; l < 4; ++l) {
        int R = mw * 32 + (l >> 1) * 16 + (l & 1) * 8 + (lane >> 2);
        rb1[R * 8 + slot] = b1[l]; ri1[R * 8 + slot] = i1[l];
        rb2[R * 8 + slot] = b2[l]; ri2[R * 8 + slot] = i2[l];
        rb3[R * 8 + slot] = b3[l]; ri3[R * 8 + slot] = i3[l];
    }
    if (tid == 0) s_cc = 0;
    __syncthreads();

    float lsum = 0.f;
    if (tid < 128) {
        float B1 = 3.4e38f, B2 = 3.4e38f;
        int I1 = 0x7fffffff;
        #pragma unroll
        for (int s = 0; s < 8; ++s) {
            int base = tid * 8 + s;
            float v; int iv;
            v = rb1[base]; iv = ri1[base];
            if (v < B1 || (v == B1 && iv < I1)) { B2 = B1; B1 = v; I1 = iv; }
            else if (v < B2) B2 = v;
            v = rb2[base]; iv = ri2[base];
            if (v < B1 || (v == B1 && iv < I1)) { B2 = B1; B1 = v; I1 = iv; }
            else if (v < B2) B2 = v;
            v = rb3[base]; iv = ri3[base];
            if (v < B1 || (v == B1 && iv < I1)) { B2 = B1; B1 = v; I1 = iv; }
            else if (v < B2) B2 = v;
        }
        s_idx[tid] = I1;
        lsum = B1;
        if (B2 - B1 < THETA) {
            int p = atomicAdd(&s_cc, 1);
            s_cnl[p] = tid;
        }
    }
    __syncthreads();

    // ---- in-CTA exact fix of contested rows (warp per row, smem cands) ----
    const int cc = s_cc;
    for (int j = warp; j < cc; j += 8) {
        const int R = s_cnl[j];
        const float* zr = z + (size_t)b * 262144 + hw0 + R;
        float zv[8];
        #pragma unroll
        for (int i = 0; i < 8; ++i)
            zv[i] = zr[(size_t)(lane + 32 * i) * 1024];
        double za = 0.0;
        #pragma unroll
        for (int i = 0; i < 8; ++i) za += (double)zv[i] * zv[i];
        #pragma unroll
        for (int o = 16; o; o >>= 1)
            za += __shfl_xor_sync(0xffffffffu, za, o);
        const float zn = (float)za;

        int kc24[24];
        #pragma unroll
        for (int s = 0; s < 8; ++s) {
            kc24[s * 3 + 0] = ri1[R * 8 + s];
            kc24[s * 3 + 1] = ri2[R * 8 + s];
            kc24[s * 3 + 2] = ri3[R * 8 + s];
        }

        float bd = 3.4e38f;
        int   bi = 0x7fffffff;
        #pragma unroll 1
        for (int jb = 0; jb < 24; jb += 4) {
            float ac[4] = {0.f, 0.f, 0.f, 0.f};
            #pragma unroll
            for (int i = 0; i < 8; ++i) {
                #pragma unroll
                for (int q = 0; q < 4; ++q)
                    ac[q] = fmaf(zv[i],
                                 E[(size_t)kc24[jb + q] * 256 + lane + 32 * i],
                                 ac[q]);
            }
            #pragma unroll
            for (int o = 16; o; o >>= 1) {
                #pragma unroll
                for (int q = 0; q < 4; ++q)
                    ac[q] += __shfl_xor_sync(0xffffffffu, ac[q], o);
            }
            #pragma unroll
            for (int q = 0; q < 4; ++q) {
                const int k = kc24[jb + q];
                float di = (zn - 2.0f * ac[q]) + g_enorm[k];
                if (di < bd || (di == bd && k < bi)) { bd = di; bi = k; }
            }
        }
        if (lane == 0) s_idx[R] = bi;
    }
    __syncthreads();

    // ---- final indices out ----
    if (tid < 128) {
        const int n = n0 + tid;
        g_indices[n] = s_idx[tid];
        out[(size_t)OFF_IDX + n] = (float)s_idx[tid];
    }

    // ---- loss partial (best scores + ||z||^2 from prologue) ----
    float v = zs + lsum;
    #pragma unroll
    for (int o = 16; o; o >>= 1) v += __shfl_down_sync(0xffffffffu, v, o);
    if (lane == 0) lws[warp] = v;
    __syncthreads();
    if (tid == 0) {
        float tot = 0.f;
        #pragma unroll
        for (int i = 0; i < 8; ++i) tot += lws[i];
        atomicAdd(&g_loss_sc, tot);
    }
}

// ---------------------------------------------------------------------------
// Kernel 3: fused gather/scatter (high-occupancy).
// z_q_st = fl(z + fl(E[idx]-z)), float4 RED scatter, counts.
// (||z||^2 loss partial now computed in k_mma's prologue.)
// ---------------------------------------------------------------------------
__global__ __launch_bounds__(256)
void k_gather(const float* __restrict__ z, const float* __restrict__ E,
              float* __restrict__ out) {
    __shared__ float es[32 * 260];
    __shared__ int   sidx[32];
    const int t   = threadIdx.x;
    const int n0  = blockIdx.x * 32;     // grid 1024
    const int b   = n0 >> 10;
    const int rem = n0 & 1023;

    if (t < 32) {
        int k = g_indices[n0 + t];
        sidx[t] = k;
        atomicAdd(&g_counts[k], 1.0f);
    }
    __syncthreads();

    #pragma unroll
    for (int k = 0; k < 32; ++k)
        es[k * 260 + t] = E[(size_t)sidx[k] * 256 + t];
    __syncthreads();

    const float* zb = z   + (size_t)b * 262144 + rem;
    float*       qb = out + (size_t)b * 262144 + rem;

    #pragma unroll 2
    for (int it = 0; it < 8; ++it) {
        int idx = t + it * 256;          // 0..2047
        int nl  = idx & 31;
        int d4  = idx >> 5;              // 0..63
        int d   = d4 << 2;
        float4 e = *(const float4*)&es[nl * 260 + d];
        float z0 = zb[(size_t)(d + 0) * 1024 + nl];
        float z1 = zb[(size_t)(d + 1) * 1024 + nl];
        float z2 = zb[(size_t)(d + 2) * 1024 + nl];
        float z3 = zb[(size_t)(d + 3) * 1024 + nl];
        qb[(size_t)(d + 0) * 1024 + nl] = z0 + (e.x - z0);
        qb[(size_t)(d + 1) * 1024 + nl] = z1 + (e.y - z1);
        qb[(size_t)(d + 2) * 1024 + nl] = z2 + (e.z - z2);
        qb[(size_t)(d + 3) * 1024 + nl] = z3 + (e.w - z3);
        atomicAdd(&g_embed_sum4[(size_t)sidx[nl] * 64 + d4],
                  make_float4(z0, z1, z2, z3));
    }
}

// ---------------------------------------------------------------------------
// Kernel 4: merged EMA epilogue.
// ---------------------------------------------------------------------------
__global__ __launch_bounds__(1024)
void k_emb(const float* __restrict__ cs_in, const float* __restrict__ es_in,
           float* __restrict__ out) {
    __shared__ float s_n;
    const int tid = threadIdx.x;
    const int i = blockIdx.x * 1024 + tid;   // grid 256 -> 262144

    if (tid < 32) {
        float s = 0.f;
        #pragma unroll
        for (int j = 0; j < 32; ++j) s += cs_in[tid + j * 32];
        #pragma unroll
        for (int o = 16; o; o >>= 1) s += __shfl_xor_sync(0xffffffffu, s, o);
        if (tid == 0) s_n = 0.99f * s + 327.68f;
    }
    __syncthreads();

    const int k = i >> 8;
    float c = 0.99f * cs_in[k] + 0.01f * g_counts[k];
    if ((i & 255) == 0) out[(size_t)OFF_CS + k] = c;
    float n  = s_n;
    float cl = (c + 1e-5f) / (n + 0.01024f) * n;
    float es = 0.99f * es_in[i] + 0.01f * ((const float*)g_embed_sum4)[i];
    out[(size_t)OFF_ES  + i] = es;
    out[(size_t)OFF_EMB + i] = es / cl;
    if (i == 0)
        out[OFF_LOSS] = g_loss_sc * (1.0f / 8388608.0f);
}

// ---------------------------------------------------------------------------
extern "C" void kernel_launch(void* const* d_in, const int* in_sizes, int n_in,
                              void* d_out, int out_size) {
    const float* z  = (const float*)d_in[0];
    const float* E  = (const float*)d_in[1];
    const float* cs = (const float*)d_in[2];
    const float* es = (const float*)d_in[3];
    float* out = (float*)d_out;

    cudaFuncSetAttribute(k_mma, cudaFuncAttributeMaxDynamicSharedMemorySize,
                         SMEM_MMA_TOTAL);

    k_init  <<<1024, 256>>>(E, out);
    k_mma   <<< 256, 256, SMEM_MMA_TOTAL>>>(z, E, out);
    k_gather<<<1024, 256>>>(z, E, out);
    k_emb   <<< 256, 1024>>>(cs, es, out);
}